// round 1
// baseline (speedup 1.0000x reference)
#include <cuda_runtime.h>
#include <math.h>

// Problem constants
#define Bn   16384
#define Sn   16
#define Dn   64
#define Hn   4
#define Fn   256
#define NB   8            // batches per CTA
#define TOK  128          // NB * Sn tokens per CTA
#define LDT  68           // padded row stride for token-major smem tiles
#define NTH  256
#define EPSV 1e-5f
#define SCL  0.25f        // 1/sqrt(D/H) = 1/sqrt(16)

// Register-tiled GEMM: acc[4][8] += A[r0..r0+3, 0..63] (stride LDT) @ Bm[0..63, c0..c0+7] (stride 64)
__device__ __forceinline__ void gemm_acc(const float* __restrict__ A,
                                         const float* __restrict__ Bm,
                                         int r0, int c0, float (&acc)[4][8]) {
#pragma unroll 2
    for (int k4 = 0; k4 < 64; k4 += 4) {
        float a[4][4];
#pragma unroll
        for (int i = 0; i < 4; ++i) {
            float4 t = *(const float4*)(A + (r0 + i) * LDT + k4);
            a[i][0] = t.x; a[i][1] = t.y; a[i][2] = t.z; a[i][3] = t.w;
        }
#pragma unroll
        for (int kk = 0; kk < 4; ++kk) {
            float4 b0 = *(const float4*)(Bm + (k4 + kk) * 64 + c0);
            float4 b1 = *(const float4*)(Bm + (k4 + kk) * 64 + c0 + 4);
#pragma unroll
            for (int i = 0; i < 4; ++i) {
                float av = a[i][kk];
                acc[i][0] = fmaf(av, b0.x, acc[i][0]);
                acc[i][1] = fmaf(av, b0.y, acc[i][1]);
                acc[i][2] = fmaf(av, b0.z, acc[i][2]);
                acc[i][3] = fmaf(av, b0.w, acc[i][3]);
                acc[i][4] = fmaf(av, b1.x, acc[i][4]);
                acc[i][5] = fmaf(av, b1.y, acc[i][5]);
                acc[i][6] = fmaf(av, b1.z, acc[i][6]);
                acc[i][7] = fmaf(av, b1.w, acc[i][7]);
            }
        }
    }
}

__device__ __forceinline__ void store_tile(float* __restrict__ Sm, int r0, int c0,
                                           const float (&acc)[4][8], bool relu) {
#pragma unroll
    for (int i = 0; i < 4; ++i) {
        float4 t0, t1;
        if (relu) {
            t0 = make_float4(fmaxf(acc[i][0], 0.f), fmaxf(acc[i][1], 0.f),
                             fmaxf(acc[i][2], 0.f), fmaxf(acc[i][3], 0.f));
            t1 = make_float4(fmaxf(acc[i][4], 0.f), fmaxf(acc[i][5], 0.f),
                             fmaxf(acc[i][6], 0.f), fmaxf(acc[i][7], 0.f));
        } else {
            t0 = make_float4(acc[i][0], acc[i][1], acc[i][2], acc[i][3]);
            t1 = make_float4(acc[i][4], acc[i][5], acc[i][6], acc[i][7]);
        }
        *(float4*)(Sm + (r0 + i) * LDT + c0)     = t0;
        *(float4*)(Sm + (r0 + i) * LDT + c0 + 4) = t1;
    }
}

// LayerNorm over 64-wide rows; 2 threads per row (pair within a warp), src stride arbitrary, dst stride LDT.
__device__ __forceinline__ void layernorm_rows(const float* __restrict__ src, int src_stride,
                                               const float* __restrict__ g,
                                               const float* __restrict__ bb,
                                               float* __restrict__ dst, int tid) {
    int r = tid >> 1, half = tid & 1;
    const float* sp = src + r * src_stride + half * 32;
    float4 v[8];
#pragma unroll
    for (int i = 0; i < 8; ++i) v[i] = *(const float4*)(sp + i * 4);
    float s = 0.f, ss = 0.f;
#pragma unroll
    for (int i = 0; i < 8; ++i) {
        s  += v[i].x + v[i].y + v[i].z + v[i].w;
        ss += v[i].x * v[i].x + v[i].y * v[i].y + v[i].z * v[i].z + v[i].w * v[i].w;
    }
    s  += __shfl_xor_sync(0xffffffffu, s, 1);
    ss += __shfl_xor_sync(0xffffffffu, ss, 1);
    float mean = s * (1.f / 64.f);
    float inv  = rsqrtf(ss * (1.f / 64.f) - mean * mean + EPSV);
    float* dp = dst + r * LDT + half * 32;
#pragma unroll
    for (int i = 0; i < 8; ++i) {
        int d = half * 32 + i * 4;
        float4 o;
        o.x = (v[i].x - mean) * inv * __ldg(g + d + 0) + __ldg(bb + d + 0);
        o.y = (v[i].y - mean) * inv * __ldg(g + d + 1) + __ldg(bb + d + 1);
        o.z = (v[i].z - mean) * inv * __ldg(g + d + 2) + __ldg(bb + d + 2);
        o.w = (v[i].w - mean) * inv * __ldg(g + d + 3) + __ldg(bb + d + 3);
        *(float4*)(dp + i * 4) = o;
    }
}

__global__ void __launch_bounds__(NTH, 1)
tblock_kernel(const float* __restrict__ x,
              const float* __restrict__ Wq, const float* __restrict__ bq,
              const float* __restrict__ Wk, const float* __restrict__ bk,
              const float* __restrict__ Wv, const float* __restrict__ bv,
              const float* __restrict__ Wp, const float* __restrict__ bp,
              const float* __restrict__ W1, const float* __restrict__ b1,
              const float* __restrict__ W2, const float* __restrict__ b2,
              const float* __restrict__ g1, const float* __restrict__ be1,
              const float* __restrict__ g2, const float* __restrict__ be2,
              float* __restrict__ out) {
    extern __shared__ float smem[];
    float* sh = smem;                 // [TOK][LDT] : LN1 out, later LN2 out
    float* sq = sh + TOK * LDT;       // Q, then ctx, then FFN hidden
    float* sk = sq + TOK * LDT;       // K, then x2 (attn residual)
    float* sv = sk + TOK * LDT;       // V
    float* sw = sv + TOK * LDT;       // 3*4096 floats of staged weights

    const int tid = threadIdx.x;
    const int g0  = blockIdx.x * TOK;     // global token offset of this tile
    const int tr  = tid >> 3;             // 0..31 -> rows tr*4..tr*4+3
    const int tc  = tid & 7;              // 0..7  -> cols tc*8..tc*8+7
    const int r0  = tr * 4, c0 = tc * 8;

    // ---------------- LN1: x -> sh ----------------
    layernorm_rows(x + (size_t)g0 * Dn, Dn, g1, be1, sh, tid);
    __syncthreads();

    // attention-out (post-proj) accumulator, init with bp
    float pacc[4][8];
#pragma unroll
    for (int j = 0; j < 8; ++j) {
        float bv_ = __ldg(bp + c0 + j);
#pragma unroll
        for (int i = 0; i < 4; ++i) pacc[i][j] = bv_;
    }

    // ---------------- per-head: QKV -> attention -> proj-accumulate ----------------
#pragma unroll 1
    for (int h = 0; h < Hn; ++h) {
        // stage Wq[h], Wk[h], Wv[h] (each 64x64) into sw
        {
            const float4* s0 = (const float4*)(Wq + h * 4096);
            const float4* s1 = (const float4*)(Wk + h * 4096);
            const float4* s2 = (const float4*)(Wv + h * 4096);
            float4* dw = (float4*)sw;
#pragma unroll
            for (int i = 0; i < 4; ++i) {
                int idx = tid + i * 256;
                dw[idx]        = s0[idx];
                dw[idx + 1024] = s1[idx];
                dw[idx + 2048] = s2[idx];
            }
        }
        __syncthreads();

        // Q = h @ Wq + bq ; K, V likewise
        {
            float acc[4][8];
#pragma unroll
            for (int j = 0; j < 8; ++j) {
                float bv_ = __ldg(bq + h * 64 + c0 + j);
#pragma unroll
                for (int i = 0; i < 4; ++i) acc[i][j] = bv_;
            }
            gemm_acc(sh, sw, r0, c0, acc);
            store_tile(sq, r0, c0, acc, false);
        }
        {
            float acc[4][8];
#pragma unroll
            for (int j = 0; j < 8; ++j) {
                float bv_ = __ldg(bk + h * 64 + c0 + j);
#pragma unroll
                for (int i = 0; i < 4; ++i) acc[i][j] = bv_;
            }
            gemm_acc(sh, sw + 4096, r0, c0, acc);
            store_tile(sk, r0, c0, acc, false);
        }
        {
            float acc[4][8];
#pragma unroll
            for (int j = 0; j < 8; ++j) {
                float bv_ = __ldg(bv + h * 64 + c0 + j);
#pragma unroll
                for (int i = 0; i < 4; ++i) acc[i][j] = bv_;
            }
            gemm_acc(sh, sw + 8192, r0, c0, acc);
            store_tile(sv, r0, c0, acc, false);
        }
        __syncthreads();

        // causal attention, one warp per batch; ctx overwrites Q rows in sq
        {
            const int w    = tid >> 5;        // batch within tile
            const int lane = tid & 31;
            const int r    = lane >> 1;       // query row 0..15
            const int half = lane & 1;
            const int t0   = half * 8;        // key cols handled by this lane
            const int base = w * 16;

            float sc[8];
#pragma unroll
            for (int j = 0; j < 8; ++j) sc[j] = 0.f;
#pragma unroll
            for (int k = 0; k < 64; k += 4) {
                float4 qv = *(const float4*)(sq + (base + r) * LDT + k);
#pragma unroll
                for (int j = 0; j < 8; ++j) {
                    float4 kv = *(const float4*)(sk + (base + t0 + j) * LDT + k);
                    sc[j] += qv.x * kv.x + qv.y * kv.y + qv.z * kv.z + qv.w * kv.w;
                }
            }
            float m = -1e30f;
#pragma unroll
            for (int j = 0; j < 8; ++j) {
                int t = t0 + j;
                sc[j] = (t <= r) ? sc[j] * SCL : -1e30f;
                m = fmaxf(m, sc[j]);
            }
            m = fmaxf(m, __shfl_xor_sync(0xffffffffu, m, 1));
            float ssum = 0.f;
#pragma unroll
            for (int j = 0; j < 8; ++j) {
                sc[j] = __expf(sc[j] - m);
                ssum += sc[j];
            }
            ssum += __shfl_xor_sync(0xffffffffu, ssum, 1);
            float inv = 1.f / ssum;

            float att[16];
#pragma unroll
            for (int j = 0; j < 8; ++j) att[t0 + j] = sc[j] * inv;
#pragma unroll
            for (int j = 0; j < 8; ++j)
                att[(t0 ^ 8) + j] = __shfl_xor_sync(0xffffffffu, sc[j], 1) * inv;

            const int d0 = half * 32;
            float4 c4[8];
#pragma unroll
            for (int j = 0; j < 8; ++j) c4[j] = make_float4(0.f, 0.f, 0.f, 0.f);
#pragma unroll
            for (int t = 0; t < 16; ++t) {
                float a = att[t];
                const float* vrow = sv + (base + t) * LDT + d0;
#pragma unroll
                for (int j = 0; j < 8; ++j) {
                    float4 vv = *(const float4*)(vrow + j * 4);
                    c4[j].x += a * vv.x; c4[j].y += a * vv.y;
                    c4[j].z += a * vv.z; c4[j].w += a * vv.w;
                }
            }
            __syncwarp();
            float* crow = sq + (base + r) * LDT + d0;
#pragma unroll
            for (int j = 0; j < 8; ++j) *(float4*)(crow + j * 4) = c4[j];
        }
        __syncthreads();

        // stage Wp rows [h*64 .. h*64+63]
        {
            const float4* s0 = (const float4*)(Wp + h * 4096);
            float4* dw = (float4*)sw;
#pragma unroll
            for (int i = 0; i < 4; ++i) dw[tid + i * 256] = s0[tid + i * 256];
        }
        __syncthreads();

        // pacc += ctx @ Wp_h
        gemm_acc(sq, sw, r0, c0, pacc);
        __syncthreads();
    }

    // ---------------- x2 = x + attn_out -> sk ----------------
#pragma unroll
    for (int i = 0; i < 4; ++i) {
        const float4* xr = (const float4*)(x + (size_t)(g0 + r0 + i) * Dn + c0);
        float4 xa = xr[0], xb = xr[1];
        float4 t0 = make_float4(xa.x + pacc[i][0], xa.y + pacc[i][1],
                                xa.z + pacc[i][2], xa.w + pacc[i][3]);
        float4 t1 = make_float4(xb.x + pacc[i][4], xb.y + pacc[i][5],
                                xb.z + pacc[i][6], xb.w + pacc[i][7]);
        *(float4*)(sk + (r0 + i) * LDT + c0)     = t0;
        *(float4*)(sk + (r0 + i) * LDT + c0 + 4) = t1;
    }
    __syncthreads();

    // ---------------- LN2: sk -> sh ----------------
    layernorm_rows(sk, LDT, g2, be2, sh, tid);
    __syncthreads();

    // ---------------- FFN in 4 chunks of 64 hidden units ----------------
    float oacc[4][8];
#pragma unroll
    for (int j = 0; j < 8; ++j) {
        float bv_ = __ldg(b2 + c0 + j);
#pragma unroll
        for (int i = 0; i < 4; ++i) oacc[i][j] = bv_;
    }

#pragma unroll 1
    for (int cc = 0; cc < 4; ++cc) {
        // stage W1[:, cc*64 .. +63] -> sw, W2[cc*64 .. +63, :] -> sw+4096
        {
            float4* dw = (float4*)sw;
            const float4* s2 = (const float4*)(W2 + cc * 4096);
#pragma unroll
            for (int i = 0; i < 4; ++i) {
                int idx = tid + i * 256;
                int k   = idx >> 4;      // 0..63
                int c4i = idx & 15;      // float4 within 64-wide row
                dw[idx]        = *(const float4*)(W1 + k * 256 + cc * 64 + c4i * 4);
                dw[idx + 1024] = s2[idx];
            }
        }
        __syncthreads();

        // hidden = relu(h2 @ W1c + b1c) -> sq
        {
            float acc[4][8];
#pragma unroll
            for (int j = 0; j < 8; ++j) {
                float bv_ = __ldg(b1 + cc * 64 + c0 + j);
#pragma unroll
                for (int i = 0; i < 4; ++i) acc[i][j] = bv_;
            }
            gemm_acc(sh, sw, r0, c0, acc);
            store_tile(sq, r0, c0, acc, true);
        }
        __syncthreads();

        // oacc += hidden @ W2c
        gemm_acc(sq, sw + 4096, r0, c0, oacc);
        __syncthreads();
    }

    // ---------------- out = x2 + ffn ----------------
#pragma unroll
    for (int i = 0; i < 4; ++i) {
        const float* x2r = sk + (r0 + i) * LDT + c0;
        float4 o0 = make_float4(x2r[0] + oacc[i][0], x2r[1] + oacc[i][1],
                                x2r[2] + oacc[i][2], x2r[3] + oacc[i][3]);
        float4 o1 = make_float4(x2r[4] + oacc[i][4], x2r[5] + oacc[i][5],
                                x2r[6] + oacc[i][6], x2r[7] + oacc[i][7]);
        float* op = out + (size_t)(g0 + r0 + i) * Dn + c0;
        *(float4*)(op)     = o0;
        *(float4*)(op + 4) = o1;
    }
}

extern "C" void kernel_launch(void* const* d_in, const int* in_sizes, int n_in,
                              void* d_out, int out_size) {
    const float* x   = (const float*)d_in[0];
    const float* Wq  = (const float*)d_in[1];
    const float* bq  = (const float*)d_in[2];
    const float* Wk  = (const float*)d_in[3];
    const float* bk  = (const float*)d_in[4];
    const float* Wv  = (const float*)d_in[5];
    const float* bv  = (const float*)d_in[6];
    const float* Wp  = (const float*)d_in[7];
    const float* bp  = (const float*)d_in[8];
    const float* W1  = (const float*)d_in[9];
    const float* b1  = (const float*)d_in[10];
    const float* W2  = (const float*)d_in[11];
    const float* b2  = (const float*)d_in[12];
    const float* g1  = (const float*)d_in[13];
    const float* be1 = (const float*)d_in[14];
    const float* g2  = (const float*)d_in[15];
    const float* be2 = (const float*)d_in[16];
    float* out = (float*)d_out;

    const int smem_bytes = (4 * TOK * LDT + 3 * 4096) * (int)sizeof(float); // 188416
    cudaFuncSetAttribute(tblock_kernel, cudaFuncAttributeMaxDynamicSharedMemorySize, smem_bytes);

    dim3 grid(Bn / NB);
    dim3 block(NTH);
    tblock_kernel<<<grid, block, smem_bytes>>>(x, Wq, bq, Wk, bk, Wv, bv, Wp, bp,
                                               W1, b1, W2, b2, g1, be1, g2, be2, out);
}

// round 2
// speedup vs baseline: 6.5232x; 6.5232x over previous
#include <cuda_runtime.h>
#include <cuda_fp16.h>
#include <math.h>
#include <stdint.h>

#define Bn   16384
#define TOK  128          // tokens per CTA (8 batches x 16)
#define LDH  72           // half stride (144B rows -> conflict-free ldmatrix)
#define LDF  68           // float stride for x2 buffer
#define NTH  256
#define EPSV 1e-5f
#define SCL  0.25f

// ---------------- PTX helpers ----------------
__device__ __forceinline__ uint32_t cvta_s(const void* p) {
    return (uint32_t)__cvta_generic_to_shared(p);
}
__device__ __forceinline__ void ldsm_x4(uint32_t* r, uint32_t a) {
    asm volatile("ldmatrix.sync.aligned.m8n8.x4.shared.b16 {%0,%1,%2,%3}, [%4];"
                 : "=r"(r[0]), "=r"(r[1]), "=r"(r[2]), "=r"(r[3]) : "r"(a));
}
__device__ __forceinline__ void ldsm_x4_t(uint32_t* r, uint32_t a) {
    asm volatile("ldmatrix.sync.aligned.m8n8.x4.trans.shared.b16 {%0,%1,%2,%3}, [%4];"
                 : "=r"(r[0]), "=r"(r[1]), "=r"(r[2]), "=r"(r[3]) : "r"(a));
}
__device__ __forceinline__ void mma16816(float* d, const uint32_t* a, const uint32_t* b) {
    asm volatile("mma.sync.aligned.m16n8k16.row.col.f32.f16.f16.f32 "
                 "{%0,%1,%2,%3},{%4,%5,%6,%7},{%8,%9},{%0,%1,%2,%3};"
                 : "+f"(d[0]), "+f"(d[1]), "+f"(d[2]), "+f"(d[3])
                 : "r"(a[0]), "r"(a[1]), "r"(a[2]), "r"(a[3]), "r"(b[0]), "r"(b[1]));
}
__device__ __forceinline__ uint32_t h2u(float a, float b) {
    __half2 h = __floats2half2_rn(a, b);
    return *(uint32_t*)&h;
}

// ---------------- warp GEMM: C[32x32] tile of C[128,64] = A[128,64] @ B[64,64] ----------------
// A, B in smem (half, stride LDH). B stored row-major [k][n]; loaded col-major via ldsm.trans.
__device__ __forceinline__ void wgemm(const __half* A, const __half* B,
                                      int mr0, int nc0, int offA, float acc[2][4][4]) {
    uint32_t aB = cvta_s(A), bB = cvta_s(B);
#pragma unroll
    for (int k0 = 0; k0 < 64; k0 += 16) {
        uint32_t a0[4], a1[4], b0[4], b1[4];
        ldsm_x4(a0, aB + 2u * (uint32_t)(mr0 * LDH + k0 + offA));
        ldsm_x4(a1, aB + 2u * (uint32_t)((mr0 + 16) * LDH + k0 + offA));
        ldsm_x4_t(b0, bB + 2u * (uint32_t)(k0 * LDH + nc0 + offA));
        ldsm_x4_t(b1, bB + 2u * (uint32_t)(k0 * LDH + nc0 + 16 + offA));
#pragma unroll
        for (int mi = 0; mi < 2; ++mi) {
            const uint32_t* aa = mi ? a1 : a0;
            mma16816(acc[mi][0], aa, b0);
            mma16816(acc[mi][1], aa, b0 + 2);
            mma16816(acc[mi][2], aa, b1);
            mma16816(acc[mi][3], aa, b1 + 2);
        }
    }
}

__device__ __forceinline__ void init_bias(float acc[2][4][4], const float* bias,
                                          int nc0, int lane) {
    int c2 = 2 * (lane & 3);
#pragma unroll
    for (int j = 0; j < 4; ++j) {
        float2 bv = *(const float2*)(bias + nc0 + 8 * j + c2);
#pragma unroll
        for (int mi = 0; mi < 2; ++mi) {
            acc[mi][j][0] = bv.x; acc[mi][j][1] = bv.y;
            acc[mi][j][2] = bv.x; acc[mi][j][3] = bv.y;
        }
    }
}

__device__ __forceinline__ void store_half_tile(__half* C, int mr0, int nc0, int lane,
                                                const float acc[2][4][4], bool relu) {
    int r = lane >> 2, c2 = 2 * (lane & 3);
#pragma unroll
    for (int mi = 0; mi < 2; ++mi)
#pragma unroll
        for (int j = 0; j < 4; ++j) {
            float v0 = acc[mi][j][0], v1 = acc[mi][j][1];
            float v2 = acc[mi][j][2], v3 = acc[mi][j][3];
            if (relu) {
                v0 = fmaxf(v0, 0.f); v1 = fmaxf(v1, 0.f);
                v2 = fmaxf(v2, 0.f); v3 = fmaxf(v3, 0.f);
            }
            int row = mr0 + 16 * mi + r, col = nc0 + 8 * j + c2;
            *(__half2*)(C + row * LDH + col)       = __floats2half2_rn(v0, v1);
            *(__half2*)(C + (row + 8) * LDH + col) = __floats2half2_rn(v2, v3);
        }
}

// stage 64x64 fp32 weight (row stride src_stride) -> half smem (stride LDH)
__device__ __forceinline__ void stage_w(const float* __restrict__ src, int src_stride,
                                        __half* dst, int tid) {
#pragma unroll
    for (int i = 0; i < 4; ++i) {
        int idx = tid + i * 256;
        int k = idx >> 4, c = (idx & 15) * 4;
        float4 v = *(const float4*)(src + k * src_stride + c);
        *(__half2*)(dst + k * LDH + c)     = __floats2half2_rn(v.x, v.y);
        *(__half2*)(dst + k * LDH + c + 2) = __floats2half2_rn(v.z, v.w);
    }
}

// LayerNorm 64-wide rows (2 threads/row), fp32 src -> half dst (stride LDH)
__device__ __forceinline__ void layernorm_half(const float* __restrict__ src, int sstride,
                                               const float* __restrict__ g,
                                               const float* __restrict__ bb,
                                               __half* dst, int tid) {
    int r = tid >> 1, hf = tid & 1;
    const float* sp = src + r * sstride + hf * 32;
    float4 v[8];
#pragma unroll
    for (int i = 0; i < 8; ++i) v[i] = *(const float4*)(sp + i * 4);
    float s = 0.f, ss = 0.f;
#pragma unroll
    for (int i = 0; i < 8; ++i) {
        s  += v[i].x + v[i].y + v[i].z + v[i].w;
        ss += v[i].x * v[i].x + v[i].y * v[i].y + v[i].z * v[i].z + v[i].w * v[i].w;
    }
    s  += __shfl_xor_sync(0xffffffffu, s, 1);
    ss += __shfl_xor_sync(0xffffffffu, ss, 1);
    float mean = s * (1.f / 64.f);
    float inv  = rsqrtf(ss * (1.f / 64.f) - mean * mean + EPSV);
    __half* dp = dst + r * LDH + hf * 32;
#pragma unroll
    for (int i = 0; i < 8; ++i) {
        int d = hf * 32 + i * 4;
        float o0 = (v[i].x - mean) * inv * __ldg(g + d + 0) + __ldg(bb + d + 0);
        float o1 = (v[i].y - mean) * inv * __ldg(g + d + 1) + __ldg(bb + d + 1);
        float o2 = (v[i].z - mean) * inv * __ldg(g + d + 2) + __ldg(bb + d + 2);
        float o3 = (v[i].w - mean) * inv * __ldg(g + d + 3) + __ldg(bb + d + 3);
        *(__half2*)(dp + i * 4)     = __floats2half2_rn(o0, o1);
        *(__half2*)(dp + i * 4 + 2) = __floats2half2_rn(o2, o3);
    }
}

// per-warp causal attention for one batch (16x16), heads handled by caller loop.
// Reads sQ/sK/sV (half), writes ctx (half) back into sQ rows of this batch.
__device__ __forceinline__ void attention_warp(__half* sQ, const __half* sK, const __half* sV,
                                               int w, int lane, int offA, int offK) {
    const int base = w * 16;
    uint32_t qB = cvta_s(sQ), kB = cvta_s(sK), vB = cvta_s(sV);

    float s0[4] = {0.f, 0.f, 0.f, 0.f};
    float s1[4] = {0.f, 0.f, 0.f, 0.f};
#pragma unroll
    for (int k0 = 0; k0 < 64; k0 += 16) {
        uint32_t aq[4], kb[4];
        ldsm_x4(aq, qB + 2u * (uint32_t)(base * LDH + k0 + offA));
        ldsm_x4(kb, kB + 2u * (uint32_t)(base * LDH + k0 + offK));
        mma16816(s0, aq, kb);
        mma16816(s1, aq, kb + 2);
    }
    const int r = lane >> 2, c2 = 2 * (lane & 3);

    float sc[2][4];
#pragma unroll
    for (int t = 0; t < 2; ++t) {
        const float* sv_ = t ? s1 : s0;
#pragma unroll
        for (int q = 0; q < 4; ++q) {
            int row = r + ((q >> 1) * 8);
            int col = 8 * t + c2 + (q & 1);
            sc[t][q] = (col <= row) ? sv_[q] * SCL : -1e30f;
        }
    }
    float m0 = fmaxf(fmaxf(sc[0][0], sc[0][1]), fmaxf(sc[1][0], sc[1][1]));
    float m1 = fmaxf(fmaxf(sc[0][2], sc[0][3]), fmaxf(sc[1][2], sc[1][3]));
    m0 = fmaxf(m0, __shfl_xor_sync(0xffffffffu, m0, 1));
    m0 = fmaxf(m0, __shfl_xor_sync(0xffffffffu, m0, 2));
    m1 = fmaxf(m1, __shfl_xor_sync(0xffffffffu, m1, 1));
    m1 = fmaxf(m1, __shfl_xor_sync(0xffffffffu, m1, 2));
    float p[2][4];
    float sum0 = 0.f, sum1 = 0.f;
#pragma unroll
    for (int t = 0; t < 2; ++t) {
        p[t][0] = __expf(sc[t][0] - m0); p[t][1] = __expf(sc[t][1] - m0);
        p[t][2] = __expf(sc[t][2] - m1); p[t][3] = __expf(sc[t][3] - m1);
        sum0 += p[t][0] + p[t][1];
        sum1 += p[t][2] + p[t][3];
    }
    sum0 += __shfl_xor_sync(0xffffffffu, sum0, 1);
    sum0 += __shfl_xor_sync(0xffffffffu, sum0, 2);
    sum1 += __shfl_xor_sync(0xffffffffu, sum1, 1);
    sum1 += __shfl_xor_sync(0xffffffffu, sum1, 2);
    float i0 = 1.f / sum0, i1 = 1.f / sum1;

    uint32_t aP[4];
    aP[0] = h2u(p[0][0] * i0, p[0][1] * i0);
    aP[1] = h2u(p[0][2] * i1, p[0][3] * i1);
    aP[2] = h2u(p[1][0] * i0, p[1][1] * i0);
    aP[3] = h2u(p[1][2] * i1, p[1][3] * i1);

    // ctx = P @ V -> overwrite sQ rows of this batch
#pragma unroll
    for (int d0 = 0; d0 < 64; d0 += 16) {
        uint32_t vb[4];
        ldsm_x4_t(vb, vB + 2u * (uint32_t)(base * LDH + d0 + offA));
        float c0f[4] = {0.f, 0.f, 0.f, 0.f};
        float c1f[4] = {0.f, 0.f, 0.f, 0.f};
        mma16816(c0f, aP, vb);
        mma16816(c1f, aP, vb + 2);
        *(__half2*)(sQ + (base + r) * LDH + d0 + c2)         = __floats2half2_rn(c0f[0], c0f[1]);
        *(__half2*)(sQ + (base + r + 8) * LDH + d0 + c2)     = __floats2half2_rn(c0f[2], c0f[3]);
        *(__half2*)(sQ + (base + r) * LDH + d0 + 8 + c2)     = __floats2half2_rn(c1f[0], c1f[1]);
        *(__half2*)(sQ + (base + r + 8) * LDH + d0 + 8 + c2) = __floats2half2_rn(c1f[2], c1f[3]);
    }
}

__global__ void __launch_bounds__(NTH, 1)
tblock_kernel(const float* __restrict__ x,
              const float* __restrict__ Wq, const float* __restrict__ bq,
              const float* __restrict__ Wk, const float* __restrict__ bk,
              const float* __restrict__ Wv, const float* __restrict__ bv,
              const float* __restrict__ Wp, const float* __restrict__ bp,
              const float* __restrict__ W1, const float* __restrict__ b1,
              const float* __restrict__ W2, const float* __restrict__ b2,
              const float* __restrict__ g1, const float* __restrict__ be1,
              const float* __restrict__ g2, const float* __restrict__ be2,
              float* __restrict__ out) {
    extern __shared__ __align__(16) char smraw[];
    __half* sH  = (__half*)smraw;          // LN1 / LN2 output (GEMM A)
    __half* sQ  = sH + TOK * LDH;          // Q, then ctx, then FFN hidden
    __half* sK  = sQ + TOK * LDH;
    __half* sV  = sK + TOK * LDH;
    __half* sW0 = sV + TOK * LDH;          // 3 weight slots 64xLDH
    __half* sW1 = sW0 + 64 * LDH;
    __half* sW2 = sW1 + 64 * LDH;
    float*  x2  = (float*)(sW2 + 64 * LDH);  // attn residual, fp32

    const int tid  = threadIdx.x;
    const int lane = tid & 31;
    const int w    = tid >> 5;
    const int g0   = blockIdx.x * TOK;

    const int mr0 = (w >> 1) * 32, nc0 = (w & 1) * 32;
    const int offA = (((lane >> 3) & 1) * 8 + (lane & 7)) * LDH + (lane >> 4) * 8;
    const int offK = ((lane >> 4) * 8 + (lane & 7)) * LDH + ((lane >> 3) & 1) * 8;

    // LN1: x -> sH (half)
    layernorm_half(x + (size_t)g0 * 64, 64, g1, be1, sH, tid);
    __syncthreads();

    float pacc[2][4][4];
    init_bias(pacc, bp, nc0, lane);

#pragma unroll 1
    for (int h = 0; h < 4; ++h) {
        stage_w(Wq + h * 4096, 64, sW0, tid);
        stage_w(Wk + h * 4096, 64, sW1, tid);
        stage_w(Wv + h * 4096, 64, sW2, tid);
        __syncthreads();
        {
            float acc[2][4][4];
            init_bias(acc, bq + h * 64, nc0, lane);
            wgemm(sH, sW0, mr0, nc0, offA, acc);
            store_half_tile(sQ, mr0, nc0, lane, acc, false);
        }
        {
            float acc[2][4][4];
            init_bias(acc, bk + h * 64, nc0, lane);
            wgemm(sH, sW1, mr0, nc0, offA, acc);
            store_half_tile(sK, mr0, nc0, lane, acc, false);
        }
        {
            float acc[2][4][4];
            init_bias(acc, bv + h * 64, nc0, lane);
            wgemm(sH, sW2, mr0, nc0, offA, acc);
            store_half_tile(sV, mr0, nc0, lane, acc, false);
        }
        __syncthreads();

        attention_warp(sQ, sK, sV, w, lane, offA, offK);
        __syncthreads();

        stage_w(Wp + h * 4096, 64, sW0, tid);
        __syncthreads();

        wgemm(sQ, sW0, mr0, nc0, offA, pacc);   // pacc += ctx_h @ Wp_h
        __syncthreads();
    }

    // x2 = x + attn_out  (fp32 smem)
    {
        const int r = lane >> 2, c2 = 2 * (lane & 3);
#pragma unroll
        for (int mi = 0; mi < 2; ++mi)
#pragma unroll
            for (int j = 0; j < 4; ++j) {
                int row = mr0 + 16 * mi + r, col = nc0 + 8 * j + c2;
                float2 xa = *(const float2*)(x + (size_t)(g0 + row) * 64 + col);
                float2 xb = *(const float2*)(x + (size_t)(g0 + row + 8) * 64 + col);
                x2[row * LDF + col]           = xa.x + pacc[mi][j][0];
                x2[row * LDF + col + 1]       = xa.y + pacc[mi][j][1];
                x2[(row + 8) * LDF + col]     = xb.x + pacc[mi][j][2];
                x2[(row + 8) * LDF + col + 1] = xb.y + pacc[mi][j][3];
            }
    }
    __syncthreads();

    // LN2: x2 -> sH (half)
    layernorm_half(x2, LDF, g2, be2, sH, tid);
    __syncthreads();

    float oacc[2][4][4];
    init_bias(oacc, b2, nc0, lane);

#pragma unroll 1
    for (int cc = 0; cc < 4; ++cc) {
        stage_w(W1 + cc * 64, 256, sW0, tid);        // W1[:, cc*64 .. +63]
        stage_w(W2 + cc * 64 * 64, 64, sW1, tid);    // W2[cc*64 .. +63, :]
        __syncthreads();
        {
            float acc[2][4][4];
            init_bias(acc, b1 + cc * 64, nc0, lane);
            wgemm(sH, sW0, mr0, nc0, offA, acc);
            store_half_tile(sQ, mr0, nc0, lane, acc, true);   // relu -> hidden
        }
        __syncthreads();
        wgemm(sQ, sW1, mr0, nc0, offA, oacc);        // oacc += hidden @ W2c
        __syncthreads();
    }

    // out = x2 + ffn
    {
        const int r = lane >> 2, c2 = 2 * (lane & 3);
#pragma unroll
        for (int mi = 0; mi < 2; ++mi)
#pragma unroll
            for (int j = 0; j < 4; ++j) {
                int row = mr0 + 16 * mi + r, col = nc0 + 8 * j + c2;
                float2 o0, o1;
                o0.x = x2[row * LDF + col]           + oacc[mi][j][0];
                o0.y = x2[row * LDF + col + 1]       + oacc[mi][j][1];
                o1.x = x2[(row + 8) * LDF + col]     + oacc[mi][j][2];
                o1.y = x2[(row + 8) * LDF + col + 1] + oacc[mi][j][3];
                *(float2*)(out + (size_t)(g0 + row) * 64 + col)     = o0;
                *(float2*)(out + (size_t)(g0 + row + 8) * 64 + col) = o1;
            }
    }
}

extern "C" void kernel_launch(void* const* d_in, const int* in_sizes, int n_in,
                              void* d_out, int out_size) {
    const float* x   = (const float*)d_in[0];
    const float* Wq  = (const float*)d_in[1];
    const float* bq  = (const float*)d_in[2];
    const float* Wk  = (const float*)d_in[3];
    const float* bk  = (const float*)d_in[4];
    const float* Wv  = (const float*)d_in[5];
    const float* bv  = (const float*)d_in[6];
    const float* Wp  = (const float*)d_in[7];
    const float* bp  = (const float*)d_in[8];
    const float* W1  = (const float*)d_in[9];
    const float* b1  = (const float*)d_in[10];
    const float* W2  = (const float*)d_in[11];
    const float* b2  = (const float*)d_in[12];
    const float* g1  = (const float*)d_in[13];
    const float* be1 = (const float*)d_in[14];
    const float* g2  = (const float*)d_in[15];
    const float* be2 = (const float*)d_in[16];
    float* out = (float*)d_out;

    const int smem_bytes = (4 * TOK * LDH + 3 * 64 * LDH) * 2 + TOK * LDF * 4; // 136192
    cudaFuncSetAttribute(tblock_kernel, cudaFuncAttributeMaxDynamicSharedMemorySize, smem_bytes);

    dim3 grid(Bn / 8);
    dim3 block(NTH);
    tblock_kernel<<<grid, block, smem_bytes>>>(x, Wq, bq, Wk, bk, Wv, bv, Wp, bp,
                                               W1, b1, W2, b2, g1, be1, g2, be2, out);
}

// round 3
// speedup vs baseline: 7.3404x; 1.1253x over previous
#include <cuda_runtime.h>
#include <cuda_fp16.h>
#include <math.h>
#include <stdint.h>

#define Bn   16384
#define TOK  128          // tokens per CTA (8 batches x 16)
#define LDH  72           // half stride (144B rows -> conflict-free ldmatrix)
#define LDF  68           // float stride for x2 buffer
#define NTH  256
#define EPSV 1e-5f
#define SCL  0.25f
#define MATH 4608         // 64*LDH halves per packed 64x64 matrix

// Packed fp16 weights: 16 head mats (Wq,Wk,Wv,Wp per head) + 4 W1 chunks + 4 W2 chunks
__device__ __align__(16) __half gWpack[24 * MATH];

// ---------------- PTX helpers ----------------
__device__ __forceinline__ uint32_t cvta_s(const void* p) {
    return (uint32_t)__cvta_generic_to_shared(p);
}
__device__ __forceinline__ void ldsm_x4(uint32_t* r, uint32_t a) {
    asm volatile("ldmatrix.sync.aligned.m8n8.x4.shared.b16 {%0,%1,%2,%3}, [%4];"
                 : "=r"(r[0]), "=r"(r[1]), "=r"(r[2]), "=r"(r[3]) : "r"(a));
}
__device__ __forceinline__ void ldsm_x4_t(uint32_t* r, uint32_t a) {
    asm volatile("ldmatrix.sync.aligned.m8n8.x4.trans.shared.b16 {%0,%1,%2,%3}, [%4];"
                 : "=r"(r[0]), "=r"(r[1]), "=r"(r[2]), "=r"(r[3]) : "r"(a));
}
__device__ __forceinline__ void mma16816(float* d, const uint32_t* a, const uint32_t* b) {
    asm volatile("mma.sync.aligned.m16n8k16.row.col.f32.f16.f16.f32 "
                 "{%0,%1,%2,%3},{%4,%5,%6,%7},{%8,%9},{%0,%1,%2,%3};"
                 : "+f"(d[0]), "+f"(d[1]), "+f"(d[2]), "+f"(d[3])
                 : "r"(a[0]), "r"(a[1]), "r"(a[2]), "r"(a[3]), "r"(b[0]), "r"(b[1]));
}
__device__ __forceinline__ uint32_t h2u(float a, float b) {
    __half2 h = __floats2half2_rn(a, b);
    return *(uint32_t*)&h;
}
__device__ __forceinline__ void cp_commit() { asm volatile("cp.async.commit_group;"); }
__device__ __forceinline__ void cp_wait0()  { asm volatile("cp.async.wait_group 0;"); }
__device__ __forceinline__ void copy_async(__half* dst, const __half* src, int bytes, int tid) {
    uint32_t d = cvta_s(dst);
    const char* s = (const char*)src;
    for (int off = tid * 16; off < bytes; off += NTH * 16)
        asm volatile("cp.async.cg.shared.global [%0], [%1], 16;" :: "r"(d + off), "l"(s + off));
}

// ---------------- A-fragment cache + register-A GEMM ----------------
__device__ __forceinline__ void load_afrag(const __half* A, int mr0, int offA, uint32_t af[4][8]) {
    uint32_t aB = cvta_s(A);
#pragma unroll
    for (int i = 0; i < 4; ++i) {
        ldsm_x4(&af[i][0], aB + 2u * (uint32_t)(mr0 * LDH + i * 16 + offA));
        ldsm_x4(&af[i][4], aB + 2u * (uint32_t)((mr0 + 16) * LDH + i * 16 + offA));
    }
}
__device__ __forceinline__ void wgemm_rf(const uint32_t af[4][8], const __half* B,
                                         int nc0, int offA, float acc[2][4][4]) {
    uint32_t bB = cvta_s(B);
#pragma unroll
    for (int i = 0; i < 4; ++i) {
        uint32_t b0[4], b1[4];
        ldsm_x4_t(b0, bB + 2u * (uint32_t)(i * 16 * LDH + nc0 + offA));
        ldsm_x4_t(b1, bB + 2u * (uint32_t)(i * 16 * LDH + nc0 + 16 + offA));
#pragma unroll
        for (int mi = 0; mi < 2; ++mi) {
            const uint32_t* aa = &af[i][mi * 4];
            mma16816(acc[mi][0], aa, b0);
            mma16816(acc[mi][1], aa, b0 + 2);
            mma16816(acc[mi][2], aa, b1);
            mma16816(acc[mi][3], aa, b1 + 2);
        }
    }
}
__device__ __forceinline__ void wgemm(const __half* A, const __half* B,
                                      int mr0, int nc0, int offA, float acc[2][4][4]) {
    uint32_t af[4][8];
    load_afrag(A, mr0, offA, af);
    wgemm_rf(af, B, nc0, offA, acc);
}

__device__ __forceinline__ void init_bias(float acc[2][4][4], const float* bias,
                                          int nc0, int lane) {
    int c2 = 2 * (lane & 3);
#pragma unroll
    for (int j = 0; j < 4; ++j) {
        float2 bv = *(const float2*)(bias + nc0 + 8 * j + c2);
#pragma unroll
        for (int mi = 0; mi < 2; ++mi) {
            acc[mi][j][0] = bv.x; acc[mi][j][1] = bv.y;
            acc[mi][j][2] = bv.x; acc[mi][j][3] = bv.y;
        }
    }
}

__device__ __forceinline__ void store_half_tile(__half* C, int mr0, int nc0, int lane,
                                                const float acc[2][4][4], bool relu) {
    int r = lane >> 2, c2 = 2 * (lane & 3);
#pragma unroll
    for (int mi = 0; mi < 2; ++mi)
#pragma unroll
        for (int j = 0; j < 4; ++j) {
            float v0 = acc[mi][j][0], v1 = acc[mi][j][1];
            float v2 = acc[mi][j][2], v3 = acc[mi][j][3];
            if (relu) {
                v0 = fmaxf(v0, 0.f); v1 = fmaxf(v1, 0.f);
                v2 = fmaxf(v2, 0.f); v3 = fmaxf(v3, 0.f);
            }
            int row = mr0 + 16 * mi + r, col = nc0 + 8 * j + c2;
            *(__half2*)(C + row * LDH + col)       = __floats2half2_rn(v0, v1);
            *(__half2*)(C + (row + 8) * LDH + col) = __floats2half2_rn(v2, v3);
        }
}

// LayerNorm 64-wide rows (2 threads/row), fp32 src -> half dst (stride LDH)
__device__ __forceinline__ void layernorm_half(const float* __restrict__ src, int sstride,
                                               const float* __restrict__ g,
                                               const float* __restrict__ bb,
                                               __half* dst, int tid) {
    int r = tid >> 1, hf = tid & 1;
    const float* sp = src + r * sstride + hf * 32;
    float4 v[8];
#pragma unroll
    for (int i = 0; i < 8; ++i) v[i] = *(const float4*)(sp + i * 4);
    float s = 0.f, ss = 0.f;
#pragma unroll
    for (int i = 0; i < 8; ++i) {
        s  += v[i].x + v[i].y + v[i].z + v[i].w;
        ss += v[i].x * v[i].x + v[i].y * v[i].y + v[i].z * v[i].z + v[i].w * v[i].w;
    }
    s  += __shfl_xor_sync(0xffffffffu, s, 1);
    ss += __shfl_xor_sync(0xffffffffu, ss, 1);
    float mean = s * (1.f / 64.f);
    float inv  = rsqrtf(ss * (1.f / 64.f) - mean * mean + EPSV);
    __half* dp = dst + r * LDH + hf * 32;
#pragma unroll
    for (int i = 0; i < 8; ++i) {
        int d = hf * 32 + i * 4;
        float o0 = (v[i].x - mean) * inv * __ldg(g + d + 0) + __ldg(bb + d + 0);
        float o1 = (v[i].y - mean) * inv * __ldg(g + d + 1) + __ldg(bb + d + 1);
        float o2 = (v[i].z - mean) * inv * __ldg(g + d + 2) + __ldg(bb + d + 2);
        float o3 = (v[i].w - mean) * inv * __ldg(g + d + 3) + __ldg(bb + d + 3);
        *(__half2*)(dp + i * 4)     = __floats2half2_rn(o0, o1);
        *(__half2*)(dp + i * 4 + 2) = __floats2half2_rn(o2, o3);
    }
}

// per-warp causal attention for one batch (16x16), heads handled by caller loop.
__device__ __forceinline__ void attention_warp(__half* sQ, const __half* sK, const __half* sV,
                                               int w, int lane, int offA, int offK) {
    const int base = w * 16;
    uint32_t qB = cvta_s(sQ), kB = cvta_s(sK), vB = cvta_s(sV);

    float s0[4] = {0.f, 0.f, 0.f, 0.f};
    float s1[4] = {0.f, 0.f, 0.f, 0.f};
#pragma unroll
    for (int k0 = 0; k0 < 64; k0 += 16) {
        uint32_t aq[4], kb[4];
        ldsm_x4(aq, qB + 2u * (uint32_t)(base * LDH + k0 + offA));
        ldsm_x4(kb, kB + 2u * (uint32_t)(base * LDH + k0 + offK));
        mma16816(s0, aq, kb);
        mma16816(s1, aq, kb + 2);
    }
    const int r = lane >> 2, c2 = 2 * (lane & 3);

    float sc[2][4];
#pragma unroll
    for (int t = 0; t < 2; ++t) {
        const float* sv_ = t ? s1 : s0;
#pragma unroll
        for (int q = 0; q < 4; ++q) {
            int row = r + ((q >> 1) * 8);
            int col = 8 * t + c2 + (q & 1);
            sc[t][q] = (col <= row) ? sv_[q] * SCL : -1e30f;
        }
    }
    float m0 = fmaxf(fmaxf(sc[0][0], sc[0][1]), fmaxf(sc[1][0], sc[1][1]));
    float m1 = fmaxf(fmaxf(sc[0][2], sc[0][3]), fmaxf(sc[1][2], sc[1][3]));
    m0 = fmaxf(m0, __shfl_xor_sync(0xffffffffu, m0, 1));
    m0 = fmaxf(m0, __shfl_xor_sync(0xffffffffu, m0, 2));
    m1 = fmaxf(m1, __shfl_xor_sync(0xffffffffu, m1, 1));
    m1 = fmaxf(m1, __shfl_xor_sync(0xffffffffu, m1, 2));
    float p[2][4];
    float sum0 = 0.f, sum1 = 0.f;
#pragma unroll
    for (int t = 0; t < 2; ++t) {
        p[t][0] = __expf(sc[t][0] - m0); p[t][1] = __expf(sc[t][1] - m0);
        p[t][2] = __expf(sc[t][2] - m1); p[t][3] = __expf(sc[t][3] - m1);
        sum0 += p[t][0] + p[t][1];
        sum1 += p[t][2] + p[t][3];
    }
    sum0 += __shfl_xor_sync(0xffffffffu, sum0, 1);
    sum0 += __shfl_xor_sync(0xffffffffu, sum0, 2);
    sum1 += __shfl_xor_sync(0xffffffffu, sum1, 1);
    sum1 += __shfl_xor_sync(0xffffffffu, sum1, 2);
    float i0 = 1.f / sum0, i1 = 1.f / sum1;

    uint32_t aP[4];
    aP[0] = h2u(p[0][0] * i0, p[0][1] * i0);
    aP[1] = h2u(p[0][2] * i1, p[0][3] * i1);
    aP[2] = h2u(p[1][0] * i0, p[1][1] * i0);
    aP[3] = h2u(p[1][2] * i1, p[1][3] * i1);

    // ctx = P @ V -> overwrite sQ rows of this batch
#pragma unroll
    for (int d0 = 0; d0 < 64; d0 += 16) {
        uint32_t vb[4];
        ldsm_x4_t(vb, vB + 2u * (uint32_t)(base * LDH + d0 + offA));
        float c0f[4] = {0.f, 0.f, 0.f, 0.f};
        float c1f[4] = {0.f, 0.f, 0.f, 0.f};
        mma16816(c0f, aP, vb);
        mma16816(c1f, aP, vb + 2);
        *(__half2*)(sQ + (base + r) * LDH + d0 + c2)         = __floats2half2_rn(c0f[0], c0f[1]);
        *(__half2*)(sQ + (base + r + 8) * LDH + d0 + c2)     = __floats2half2_rn(c0f[2], c0f[3]);
        *(__half2*)(sQ + (base + r) * LDH + d0 + 8 + c2)     = __floats2half2_rn(c1f[0], c1f[1]);
        *(__half2*)(sQ + (base + r + 8) * LDH + d0 + 8 + c2) = __floats2half2_rn(c1f[2], c1f[3]);
    }
}

// ---------------- weight pack pre-kernel ----------------
__global__ void pack_weights(const float* __restrict__ Wq, const float* __restrict__ Wk,
                             const float* __restrict__ Wv, const float* __restrict__ Wp,
                             const float* __restrict__ W1, const float* __restrict__ W2) {
    int m = blockIdx.x, tid = threadIdx.x;
    const float* base;
    int stride;
    if (m < 16) {
        int h = m >> 2, t = m & 3;
        const float* w = (t == 0) ? Wq : (t == 1) ? Wk : (t == 2) ? Wv : Wp;
        base = w + h * 4096; stride = 64;
    } else if (m < 20) {
        base = W1 + (m - 16) * 64; stride = 256;   // W1[:, cc*64 .. +63]
    } else {
        base = W2 + (m - 20) * 4096; stride = 64;  // W2[cc*64 .. +63, :]
    }
    __half* dst = gWpack + m * MATH;
#pragma unroll
    for (int j = 0; j < 4; ++j) {
        int e = tid + j * 256;          // float4 unit 0..1023
        int k = e >> 4, c4 = (e & 15) * 4;
        float4 v = *(const float4*)(base + k * stride + c4);
        *(__half2*)(dst + k * LDH + c4)     = __floats2half2_rn(v.x, v.y);
        *(__half2*)(dst + k * LDH + c4 + 2) = __floats2half2_rn(v.z, v.w);
    }
}

// ---------------- main fused kernel ----------------
__global__ void __launch_bounds__(NTH, 1)
tblock_kernel(const float* __restrict__ x,
              const float* __restrict__ bq, const float* __restrict__ bk,
              const float* __restrict__ bv, const float* __restrict__ bp,
              const float* __restrict__ b1, const float* __restrict__ b2,
              const float* __restrict__ g1, const float* __restrict__ be1,
              const float* __restrict__ g2, const float* __restrict__ be2,
              float* __restrict__ out) {
    extern __shared__ __align__(16) char smraw[];
    __half* sH = (__half*)smraw;       // 128 x LDH
    __half* sQ = sH + TOK * LDH;
    __half* sK = sQ + TOK * LDH;
    __half* sV = sK + TOK * LDH;
    __half* sW = sV + TOK * LDH;       // 2 buffers x 4 slots x MATH
    float*  x2 = (float*)sK;           // aliased: sK+sV dead after attention phase

    const int tid  = threadIdx.x;
    const int lane = tid & 31;
    const int w    = tid >> 5;
    const int g0   = blockIdx.x * TOK;

    const int mr0 = (w >> 1) * 32, nc0 = (w & 1) * 32;
    const int offA = (((lane >> 3) & 1) * 8 + (lane & 7)) * LDH + (lane >> 4) * 8;
    const int offK = ((lane >> 4) * 8 + (lane & 7)) * LDH + ((lane >> 3) & 1) * 8;

    // prefetch head-0 weights (Wq,Wk,Wv,Wp) while LN1 runs
    copy_async(sW, gWpack, 4 * MATH * 2, tid);
    cp_commit();

    // LN1: x -> sH (half)
    layernorm_half(x + (size_t)g0 * 64, 64, g1, be1, sH, tid);
    cp_wait0();
    __syncthreads();

    // cache A fragments of sH (reused for all 12 QKV GEMMs)
    uint32_t ah[4][8];
    load_afrag(sH, mr0, offA, ah);

    float pacc[2][4][4];
    init_bias(pacc, bp, nc0, lane);

#pragma unroll 1
    for (int h = 0; h < 4; ++h) {
        const __half* Wb = sW + (h & 1) * 4 * MATH;
        if (h > 0) { cp_wait0(); __syncthreads(); }

        // QKV from cached A frags
        {
            float acc[2][4][4];
            init_bias(acc, bq + h * 64, nc0, lane);
            wgemm_rf(ah, Wb, nc0, offA, acc);
            store_half_tile(sQ, mr0, nc0, lane, acc, false);
        }
        {
            float acc[2][4][4];
            init_bias(acc, bk + h * 64, nc0, lane);
            wgemm_rf(ah, Wb + MATH, nc0, offA, acc);
            store_half_tile(sK, mr0, nc0, lane, acc, false);
        }
        {
            float acc[2][4][4];
            init_bias(acc, bv + h * 64, nc0, lane);
            wgemm_rf(ah, Wb + 2 * MATH, nc0, offA, acc);
            store_half_tile(sV, mr0, nc0, lane, acc, false);
        }
        __syncthreads();

        // prefetch next head's weights into the other buffer (safe: that buffer's
        // readers finished before this head's entry sync)
        if (h < 3) {
            copy_async(sW + ((h + 1) & 1) * 4 * MATH, gWpack + (h + 1) * 4 * MATH,
                       4 * MATH * 2, tid);
            cp_commit();
        }

        attention_warp(sQ, sK, sV, w, lane, offA, offK);
        __syncthreads();

        // pacc += ctx_h @ Wp_h
        wgemm(sQ, Wb + 3 * MATH, mr0, nc0, offA, pacc);
    }
    __syncthreads();   // all proj reads of sQ / sK,sV done before x2 aliases them

    // x2 = x + attn_out (fp32, aliased over sK/sV)
    {
        const int r = lane >> 2, c2 = 2 * (lane & 3);
#pragma unroll
        for (int mi = 0; mi < 2; ++mi)
#pragma unroll
            for (int j = 0; j < 4; ++j) {
                int row = mr0 + 16 * mi + r, col = nc0 + 8 * j + c2;
                float2 xa = *(const float2*)(x + (size_t)(g0 + row) * 64 + col);
                float2 xb = *(const float2*)(x + (size_t)(g0 + row + 8) * 64 + col);
                x2[row * LDF + col]           = xa.x + pacc[mi][j][0];
                x2[row * LDF + col + 1]       = xa.y + pacc[mi][j][1];
                x2[(row + 8) * LDF + col]     = xb.x + pacc[mi][j][2];
                x2[(row + 8) * LDF + col + 1] = xb.y + pacc[mi][j][3];
            }
    }
    // prefetch FFN chunk 0 (buffer 0; its last readers were head 2, long done)
    copy_async(sW, gWpack + 16 * MATH, MATH * 2, tid);
    copy_async(sW + MATH, gWpack + 20 * MATH, MATH * 2, tid);
    cp_commit();
    __syncthreads();

    // LN2: x2 -> sH (half)
    layernorm_half(x2, LDF, g2, be2, sH, tid);
    __syncthreads();

    uint32_t ahf[4][8];
    load_afrag(sH, mr0, offA, ahf);

    float oacc[2][4][4];
    init_bias(oacc, b2, nc0, lane);

#pragma unroll 1
    for (int cc = 0; cc < 4; ++cc) {
        const __half* Wb = sW + (cc & 1) * 4 * MATH;
        cp_wait0();
        __syncthreads();

        // hidden = relu(h2 @ W1c + b1c) -> sQ
        {
            float acc[2][4][4];
            init_bias(acc, b1 + cc * 64, nc0, lane);
            wgemm_rf(ahf, Wb, nc0, offA, acc);
            store_half_tile(sQ, mr0, nc0, lane, acc, true);
        }
        __syncthreads();

        if (cc < 3) {
            __half* nb = sW + ((cc + 1) & 1) * 4 * MATH;
            copy_async(nb, gWpack + (16 + cc + 1) * MATH, MATH * 2, tid);
            copy_async(nb + MATH, gWpack + (20 + cc + 1) * MATH, MATH * 2, tid);
            cp_commit();
        }

        // oacc += hidden @ W2c
        wgemm(sQ, Wb + MATH, mr0, nc0, offA, oacc);
        __syncthreads();   // protect sQ before next chunk's hidden store
    }

    // out = x2 + ffn
    {
        const int r = lane >> 2, c2 = 2 * (lane & 3);
#pragma unroll
        for (int mi = 0; mi < 2; ++mi)
#pragma unroll
            for (int j = 0; j < 4; ++j) {
                int row = mr0 + 16 * mi + r, col = nc0 + 8 * j + c2;
                float2 o0, o1;
                o0.x = x2[row * LDF + col]           + oacc[mi][j][0];
                o0.y = x2[row * LDF + col + 1]       + oacc[mi][j][1];
                o1.x = x2[(row + 8) * LDF + col]     + oacc[mi][j][2];
                o1.y = x2[(row + 8) * LDF + col + 1] + oacc[mi][j][3];
                *(float2*)(out + (size_t)(g0 + row) * 64 + col)     = o0;
                *(float2*)(out + (size_t)(g0 + row + 8) * 64 + col) = o1;
            }
    }
}

extern "C" void kernel_launch(void* const* d_in, const int* in_sizes, int n_in,
                              void* d_out, int out_size) {
    const float* x   = (const float*)d_in[0];
    const float* Wq  = (const float*)d_in[1];
    const float* bq  = (const float*)d_in[2];
    const float* Wk  = (const float*)d_in[3];
    const float* bk  = (const float*)d_in[4];
    const float* Wv  = (const float*)d_in[5];
    const float* bv  = (const float*)d_in[6];
    const float* Wp  = (const float*)d_in[7];
    const float* bp  = (const float*)d_in[8];
    const float* W1  = (const float*)d_in[9];
    const float* b1  = (const float*)d_in[10];
    const float* W2  = (const float*)d_in[11];
    const float* b2  = (const float*)d_in[12];
    const float* g1  = (const float*)d_in[13];
    const float* be1 = (const float*)d_in[14];
    const float* g2  = (const float*)d_in[15];
    const float* be2 = (const float*)d_in[16];
    float* out = (float*)d_out;

    pack_weights<<<24, 256>>>(Wq, Wk, Wv, Wp, W1, W2);

    const int smem_bytes = (4 * TOK * LDH + 2 * 4 * MATH) * 2; // 147456
    cudaFuncSetAttribute(tblock_kernel, cudaFuncAttributeMaxDynamicSharedMemorySize, smem_bytes);

    dim3 grid(Bn / 8);
    dim3 block(NTH);
    tblock_kernel<<<grid, block, smem_bytes>>>(x, bq, bk, bv, bp, b1, b2,
                                               g1, be1, g2, be2, out);
}

// round 4
// speedup vs baseline: 8.4238x; 1.1476x over previous
#include <cuda_runtime.h>
#include <cuda_fp16.h>
#include <math.h>
#include <stdint.h>

#define Bn   16384
#define TOK  128          // tokens per CTA (8 batches x 16)
#define LDH  72           // half stride (144B rows -> conflict-free ldmatrix)
#define LDF  68           // float stride for x2 buffer
#define NTH  256
#define EPSV 1e-5f
#define SCL  0.25f
#define MATH 4608         // 64*LDH halves per packed 64x64 matrix

// Packed fp16 weights: 16 head mats (Wq,Wk,Wv,Wp per head) + 4 W1 chunks + 4 W2 chunks
__device__ __align__(16) __half gWpack[24 * MATH];

// ---------------- PTX helpers ----------------
__device__ __forceinline__ uint32_t cvta_s(const void* p) {
    return (uint32_t)__cvta_generic_to_shared(p);
}
__device__ __forceinline__ void ldsm_x4(uint32_t* r, uint32_t a) {
    asm volatile("ldmatrix.sync.aligned.m8n8.x4.shared.b16 {%0,%1,%2,%3}, [%4];"
                 : "=r"(r[0]), "=r"(r[1]), "=r"(r[2]), "=r"(r[3]) : "r"(a));
}
__device__ __forceinline__ void ldsm_x4_t(uint32_t* r, uint32_t a) {
    asm volatile("ldmatrix.sync.aligned.m8n8.x4.trans.shared.b16 {%0,%1,%2,%3}, [%4];"
                 : "=r"(r[0]), "=r"(r[1]), "=r"(r[2]), "=r"(r[3]) : "r"(a));
}
__device__ __forceinline__ void mma16816(float* d, const uint32_t* a, const uint32_t* b) {
    asm volatile("mma.sync.aligned.m16n8k16.row.col.f32.f16.f16.f32 "
                 "{%0,%1,%2,%3},{%4,%5,%6,%7},{%8,%9},{%0,%1,%2,%3};"
                 : "+f"(d[0]), "+f"(d[1]), "+f"(d[2]), "+f"(d[3])
                 : "r"(a[0]), "r"(a[1]), "r"(a[2]), "r"(a[3]), "r"(b[0]), "r"(b[1]));
}
__device__ __forceinline__ uint32_t h2u(float a, float b) {
    __half2 h = __floats2half2_rn(a, b);
    return *(uint32_t*)&h;
}
__device__ __forceinline__ void cp_commit() { asm volatile("cp.async.commit_group;"); }
__device__ __forceinline__ void cp_wait0()  { asm volatile("cp.async.wait_group 0;"); }
__device__ __forceinline__ void copy_async(__half* dst, const __half* src, int bytes, int tid) {
    uint32_t d = cvta_s(dst);
    const char* s = (const char*)src;
    for (int off = tid * 16; off < bytes; off += NTH * 16)
        asm volatile("cp.async.cg.shared.global [%0], [%1], 16;" :: "r"(d + off), "l"(s + off));
}

// ---------------- A-fragment cache + register-A GEMM ----------------
__device__ __forceinline__ void load_afrag(const __half* A, int mr0, int offA, uint32_t af[4][8]) {
    uint32_t aB = cvta_s(A);
#pragma unroll
    for (int i = 0; i < 4; ++i) {
        ldsm_x4(&af[i][0], aB + 2u * (uint32_t)(mr0 * LDH + i * 16 + offA));
        ldsm_x4(&af[i][4], aB + 2u * (uint32_t)((mr0 + 16) * LDH + i * 16 + offA));
    }
}
__device__ __forceinline__ void wgemm_rf(const uint32_t af[4][8], const __half* B,
                                         int nc0, int offA, float acc[2][4][4]) {
    uint32_t bB = cvta_s(B);
#pragma unroll
    for (int i = 0; i < 4; ++i) {
        uint32_t b0[4], b1[4];
        ldsm_x4_t(b0, bB + 2u * (uint32_t)(i * 16 * LDH + nc0 + offA));
        ldsm_x4_t(b1, bB + 2u * (uint32_t)(i * 16 * LDH + nc0 + 16 + offA));
#pragma unroll
        for (int mi = 0; mi < 2; ++mi) {
            const uint32_t* aa = &af[i][mi * 4];
            mma16816(acc[mi][0], aa, b0);
            mma16816(acc[mi][1], aa, b0 + 2);
            mma16816(acc[mi][2], aa, b1);
            mma16816(acc[mi][3], aa, b1 + 2);
        }
    }
}
__device__ __forceinline__ void wgemm(const __half* A, const __half* B,
                                      int mr0, int nc0, int offA, float acc[2][4][4]) {
    uint32_t af[4][8];
    load_afrag(A, mr0, offA, af);
    wgemm_rf(af, B, nc0, offA, acc);
}

__device__ __forceinline__ void init_bias(float acc[2][4][4], const float* bias,
                                          int nc0, int lane) {
    int c2 = 2 * (lane & 3);
#pragma unroll
    for (int j = 0; j < 4; ++j) {
        float2 bv = *(const float2*)(bias + nc0 + 8 * j + c2);
#pragma unroll
        for (int mi = 0; mi < 2; ++mi) {
            acc[mi][j][0] = bv.x; acc[mi][j][1] = bv.y;
            acc[mi][j][2] = bv.x; acc[mi][j][3] = bv.y;
        }
    }
}

__device__ __forceinline__ void store_half_tile(__half* C, int mr0, int nc0, int lane,
                                                const float acc[2][4][4], bool relu) {
    int r = lane >> 2, c2 = 2 * (lane & 3);
#pragma unroll
    for (int mi = 0; mi < 2; ++mi)
#pragma unroll
        for (int j = 0; j < 4; ++j) {
            float v0 = acc[mi][j][0], v1 = acc[mi][j][1];
            float v2 = acc[mi][j][2], v3 = acc[mi][j][3];
            if (relu) {
                v0 = fmaxf(v0, 0.f); v1 = fmaxf(v1, 0.f);
                v2 = fmaxf(v2, 0.f); v3 = fmaxf(v3, 0.f);
            }
            int row = mr0 + 16 * mi + r, col = nc0 + 8 * j + c2;
            *(__half2*)(C + row * LDH + col)       = __floats2half2_rn(v0, v1);
            *(__half2*)(C + (row + 8) * LDH + col) = __floats2half2_rn(v2, v3);
        }
}

// LayerNorm 64-wide rows (2 threads/row), fp32 src -> half dst (stride LDH)
__device__ __forceinline__ void layernorm_half(const float* __restrict__ src, int sstride,
                                               const float* __restrict__ g,
                                               const float* __restrict__ bb,
                                               __half* dst, int tid) {
    int r = tid >> 1, hf = tid & 1;
    const float* sp = src + r * sstride + hf * 32;
    float4 v[8];
#pragma unroll
    for (int i = 0; i < 8; ++i) v[i] = *(const float4*)(sp + i * 4);
    float s = 0.f, ss = 0.f;
#pragma unroll
    for (int i = 0; i < 8; ++i) {
        s  += v[i].x + v[i].y + v[i].z + v[i].w;
        ss += v[i].x * v[i].x + v[i].y * v[i].y + v[i].z * v[i].z + v[i].w * v[i].w;
    }
    s  += __shfl_xor_sync(0xffffffffu, s, 1);
    ss += __shfl_xor_sync(0xffffffffu, ss, 1);
    float mean = s * (1.f / 64.f);
    float inv  = rsqrtf(ss * (1.f / 64.f) - mean * mean + EPSV);
    __half* dp = dst + r * LDH + hf * 32;
#pragma unroll
    for (int i = 0; i < 8; ++i) {
        int d = hf * 32 + i * 4;
        float o0 = (v[i].x - mean) * inv * __ldg(g + d + 0) + __ldg(bb + d + 0);
        float o1 = (v[i].y - mean) * inv * __ldg(g + d + 1) + __ldg(bb + d + 1);
        float o2 = (v[i].z - mean) * inv * __ldg(g + d + 2) + __ldg(bb + d + 2);
        float o3 = (v[i].w - mean) * inv * __ldg(g + d + 3) + __ldg(bb + d + 3);
        *(__half2*)(dp + i * 4)     = __floats2half2_rn(o0, o1);
        *(__half2*)(dp + i * 4 + 2) = __floats2half2_rn(o2, o3);
    }
}

// per-warp causal attention for one batch (16x16), heads handled by caller loop.
__device__ __forceinline__ void attention_warp(__half* sQ, const __half* sK, const __half* sV,
                                               int w, int lane, int offA, int offK) {
    const int base = w * 16;
    uint32_t qB = cvta_s(sQ), kB = cvta_s(sK), vB = cvta_s(sV);

    float s0[4] = {0.f, 0.f, 0.f, 0.f};
    float s1[4] = {0.f, 0.f, 0.f, 0.f};
#pragma unroll
    for (int k0 = 0; k0 < 64; k0 += 16) {
        uint32_t aq[4], kb[4];
        ldsm_x4(aq, qB + 2u * (uint32_t)(base * LDH + k0 + offA));
        ldsm_x4(kb, kB + 2u * (uint32_t)(base * LDH + k0 + offK));
        mma16816(s0, aq, kb);
        mma16816(s1, aq, kb + 2);
    }
    const int r = lane >> 2, c2 = 2 * (lane & 3);

    float sc[2][4];
#pragma unroll
    for (int t = 0; t < 2; ++t) {
        const float* sv_ = t ? s1 : s0;
#pragma unroll
        for (int q = 0; q < 4; ++q) {
            int row = r + ((q >> 1) * 8);
            int col = 8 * t + c2 + (q & 1);
            sc[t][q] = (col <= row) ? sv_[q] * SCL : -1e30f;
        }
    }
    float m0 = fmaxf(fmaxf(sc[0][0], sc[0][1]), fmaxf(sc[1][0], sc[1][1]));
    float m1 = fmaxf(fmaxf(sc[0][2], sc[0][3]), fmaxf(sc[1][2], sc[1][3]));
    m0 = fmaxf(m0, __shfl_xor_sync(0xffffffffu, m0, 1));
    m0 = fmaxf(m0, __shfl_xor_sync(0xffffffffu, m0, 2));
    m1 = fmaxf(m1, __shfl_xor_sync(0xffffffffu, m1, 1));
    m1 = fmaxf(m1, __shfl_xor_sync(0xffffffffu, m1, 2));
    float p[2][4];
    float sum0 = 0.f, sum1 = 0.f;
#pragma unroll
    for (int t = 0; t < 2; ++t) {
        p[t][0] = __expf(sc[t][0] - m0); p[t][1] = __expf(sc[t][1] - m0);
        p[t][2] = __expf(sc[t][2] - m1); p[t][3] = __expf(sc[t][3] - m1);
        sum0 += p[t][0] + p[t][1];
        sum1 += p[t][2] + p[t][3];
    }
    sum0 += __shfl_xor_sync(0xffffffffu, sum0, 1);
    sum0 += __shfl_xor_sync(0xffffffffu, sum0, 2);
    sum1 += __shfl_xor_sync(0xffffffffu, sum1, 1);
    sum1 += __shfl_xor_sync(0xffffffffu, sum1, 2);
    float i0 = 1.f / sum0, i1 = 1.f / sum1;

    uint32_t aP[4];
    aP[0] = h2u(p[0][0] * i0, p[0][1] * i0);
    aP[1] = h2u(p[0][2] * i1, p[0][3] * i1);
    aP[2] = h2u(p[1][0] * i0, p[1][1] * i0);
    aP[3] = h2u(p[1][2] * i1, p[1][3] * i1);

    // ctx = P @ V -> overwrite sQ rows of this batch
#pragma unroll
    for (int d0 = 0; d0 < 64; d0 += 16) {
        uint32_t vb[4];
        ldsm_x4_t(vb, vB + 2u * (uint32_t)(base * LDH + d0 + offA));
        float c0f[4] = {0.f, 0.f, 0.f, 0.f};
        float c1f[4] = {0.f, 0.f, 0.f, 0.f};
        mma16816(c0f, aP, vb);
        mma16816(c1f, aP, vb + 2);
        *(__half2*)(sQ + (base + r) * LDH + d0 + c2)         = __floats2half2_rn(c0f[0], c0f[1]);
        *(__half2*)(sQ + (base + r + 8) * LDH + d0 + c2)     = __floats2half2_rn(c0f[2], c0f[3]);
        *(__half2*)(sQ + (base + r) * LDH + d0 + 8 + c2)     = __floats2half2_rn(c1f[0], c1f[1]);
        *(__half2*)(sQ + (base + r + 8) * LDH + d0 + 8 + c2) = __floats2half2_rn(c1f[2], c1f[3]);
    }
}

// ---------------- weight pack pre-kernel ----------------
__global__ void pack_weights(const float* __restrict__ Wq, const float* __restrict__ Wk,
                             const float* __restrict__ Wv, const float* __restrict__ Wp,
                             const float* __restrict__ W1, const float* __restrict__ W2) {
    int m = blockIdx.x, tid = threadIdx.x;
    const float* base;
    int stride;
    if (m < 16) {
        int h = m >> 2, t = m & 3;
        const float* w = (t == 0) ? Wq : (t == 1) ? Wk : (t == 2) ? Wv : Wp;
        base = w + h * 4096; stride = 64;
    } else if (m < 20) {
        base = W1 + (m - 16) * 64; stride = 256;   // W1[:, cc*64 .. +63]
    } else {
        base = W2 + (m - 20) * 4096; stride = 64;  // W2[cc*64 .. +63, :]
    }
    __half* dst = gWpack + m * MATH;
#pragma unroll
    for (int j = 0; j < 4; ++j) {
        int e = tid + j * 256;          // float4 unit 0..1023
        int k = e >> 4, c4 = (e & 15) * 4;
        float4 v = *(const float4*)(base + k * stride + c4);
        *(__half2*)(dst + k * LDH + c4)     = __floats2half2_rn(v.x, v.y);
        *(__half2*)(dst + k * LDH + c4 + 2) = __floats2half2_rn(v.z, v.w);
    }
}

// ---------------- main fused kernel ----------------
__global__ void __launch_bounds__(NTH, 2)
tblock_kernel(const float* __restrict__ x,
              const float* __restrict__ bq, const float* __restrict__ bk,
              const float* __restrict__ bv, const float* __restrict__ bp,
              const float* __restrict__ b1, const float* __restrict__ b2,
              const float* __restrict__ g1, const float* __restrict__ be1,
              const float* __restrict__ g2, const float* __restrict__ be2,
              float* __restrict__ out) {
    extern __shared__ __align__(16) char smraw[];
    __half* sH = (__half*)smraw;       // 128 x LDH
    __half* sQ = sH + TOK * LDH;
    __half* sK = sQ + TOK * LDH;
    __half* sV = sK + TOK * LDH;
    __half* sW = sV + TOK * LDH;       // single buffer: 4 slots x MATH
    float*  x2 = (float*)sK;           // aliased: sK+sV dead after attention phase

    const int tid  = threadIdx.x;
    const int lane = tid & 31;
    const int w    = tid >> 5;
    const int g0   = blockIdx.x * TOK;

    const int mr0 = (w >> 1) * 32, nc0 = (w & 1) * 32;
    const int offA = (((lane >> 3) & 1) * 8 + (lane & 7)) * LDH + (lane >> 4) * 8;
    const int offK = ((lane >> 4) * 8 + (lane & 7)) * LDH + ((lane >> 3) & 1) * 8;

    // prefetch head-0 weights (Wq,Wk,Wv,Wp) while LN1 runs
    copy_async(sW, gWpack, 4 * MATH * 2, tid);
    cp_commit();

    // LN1: x -> sH (half)
    layernorm_half(x + (size_t)g0 * 64, 64, g1, be1, sH, tid);
    cp_wait0();
    __syncthreads();

    // cache A fragments of sH (reused for all 12 QKV GEMMs)
    uint32_t ah[4][8];
    load_afrag(sH, mr0, offA, ah);

    float pacc[2][4][4];
    init_bias(pacc, bp, nc0, lane);

#pragma unroll 1
    for (int h = 0; h < 4; ++h) {
        // QKV from cached A frags (weights for head h are resident in sW)
        {
            float acc[2][4][4];
            init_bias(acc, bq + h * 64, nc0, lane);
            wgemm_rf(ah, sW, nc0, offA, acc);
            store_half_tile(sQ, mr0, nc0, lane, acc, false);
        }
        {
            float acc[2][4][4];
            init_bias(acc, bk + h * 64, nc0, lane);
            wgemm_rf(ah, sW + MATH, nc0, offA, acc);
            store_half_tile(sK, mr0, nc0, lane, acc, false);
        }
        {
            float acc[2][4][4];
            init_bias(acc, bv + h * 64, nc0, lane);
            wgemm_rf(ah, sW + 2 * MATH, nc0, offA, acc);
            store_half_tile(sV, mr0, nc0, lane, acc, false);
        }
        __syncthreads();

        attention_warp(sQ, sK, sV, w, lane, offA, offK);
        __syncthreads();

        // pacc += ctx_h @ Wp_h  (last reader of sW this head)
        wgemm(sQ, sW + 3 * MATH, mr0, nc0, offA, pacc);
        __syncthreads();

        if (h < 3) {
            copy_async(sW, gWpack + (h + 1) * 4 * MATH, 4 * MATH * 2, tid);
            cp_commit();
            cp_wait0();
            __syncthreads();
        }
    }

    // x2 = x + attn_out (fp32, aliased over sK/sV — safe: post-proj sync done)
    {
        const int r = lane >> 2, c2 = 2 * (lane & 3);
#pragma unroll
        for (int mi = 0; mi < 2; ++mi)
#pragma unroll
            for (int j = 0; j < 4; ++j) {
                int row = mr0 + 16 * mi + r, col = nc0 + 8 * j + c2;
                float2 xa = *(const float2*)(x + (size_t)(g0 + row) * 64 + col);
                float2 xb = *(const float2*)(x + (size_t)(g0 + row + 8) * 64 + col);
                x2[row * LDF + col]           = xa.x + pacc[mi][j][0];
                x2[row * LDF + col + 1]       = xa.y + pacc[mi][j][1];
                x2[(row + 8) * LDF + col]     = xb.x + pacc[mi][j][2];
                x2[(row + 8) * LDF + col + 1] = xb.y + pacc[mi][j][3];
            }
    }
    // prefetch FFN chunk 0 into slots 0,1 (sW free after final proj sync)
    copy_async(sW, gWpack + 16 * MATH, MATH * 2, tid);
    copy_async(sW + MATH, gWpack + 20 * MATH, MATH * 2, tid);
    cp_commit();
    __syncthreads();

    // LN2: x2 -> sH (half)
    layernorm_half(x2, LDF, g2, be2, sH, tid);
    __syncthreads();

    uint32_t ahf[4][8];
    load_afrag(sH, mr0, offA, ahf);

    float oacc[2][4][4];
    init_bias(oacc, b2, nc0, lane);

#pragma unroll 1
    for (int cc = 0; cc < 4; ++cc) {
        const __half* Wb = sW + (cc & 1) * 2 * MATH;   // slots {0,1} or {2,3}
        cp_wait0();
        __syncthreads();

        // hidden = relu(h2 @ W1c + b1c) -> sQ
        {
            float acc[2][4][4];
            init_bias(acc, b1 + cc * 64, nc0, lane);
            wgemm_rf(ahf, Wb, nc0, offA, acc);
            store_half_tile(sQ, mr0, nc0, lane, acc, true);
        }
        __syncthreads();

        if (cc < 3) {
            __half* nb = sW + ((cc + 1) & 1) * 2 * MATH;
            copy_async(nb, gWpack + (16 + cc + 1) * MATH, MATH * 2, tid);
            copy_async(nb + MATH, gWpack + (20 + cc + 1) * MATH, MATH * 2, tid);
            cp_commit();
        }

        // oacc += hidden @ W2c
        wgemm(sQ, Wb + MATH, mr0, nc0, offA, oacc);
        __syncthreads();   // protect sQ before next chunk's hidden store
    }

    // out = x2 + ffn
    {
        const int r = lane >> 2, c2 = 2 * (lane & 3);
#pragma unroll
        for (int mi = 0; mi < 2; ++mi)
#pragma unroll
            for (int j = 0; j < 4; ++j) {
                int row = mr0 + 16 * mi + r, col = nc0 + 8 * j + c2;
                float2 o0, o1;
                o0.x = x2[row * LDF + col]           + oacc[mi][j][0];
                o0.y = x2[row * LDF + col + 1]       + oacc[mi][j][1];
                o1.x = x2[(row + 8) * LDF + col]     + oacc[mi][j][2];
                o1.y = x2[(row + 8) * LDF + col + 1] + oacc[mi][j][3];
                *(float2*)(out + (size_t)(g0 + row) * 64 + col)     = o0;
                *(float2*)(out + (size_t)(g0 + row + 8) * 64 + col) = o1;
            }
    }
}

extern "C" void kernel_launch(void* const* d_in, const int* in_sizes, int n_in,
                              void* d_out, int out_size) {
    const float* x   = (const float*)d_in[0];
    const float* Wq  = (const float*)d_in[1];
    const float* bq  = (const float*)d_in[2];
    const float* Wk  = (const float*)d_in[3];
    const float* bk  = (const float*)d_in[4];
    const float* Wv  = (const float*)d_in[5];
    const float* bv  = (const float*)d_in[6];
    const float* Wp  = (const float*)d_in[7];
    const float* bp  = (const float*)d_in[8];
    const float* W1  = (const float*)d_in[9];
    const float* b1  = (const float*)d_in[10];
    const float* W2  = (const float*)d_in[11];
    const float* b2  = (const float*)d_in[12];
    const float* g1  = (const float*)d_in[13];
    const float* be1 = (const float*)d_in[14];
    const float* g2  = (const float*)d_in[15];
    const float* be2 = (const float*)d_in[16];
    float* out = (float*)d_out;

    pack_weights<<<24, 256>>>(Wq, Wk, Wv, Wp, W1, W2);

    const int smem_bytes = (4 * TOK * LDH + 4 * MATH) * 2; // 110592
    cudaFuncSetAttribute(tblock_kernel, cudaFuncAttributeMaxDynamicSharedMemorySize, smem_bytes);

    dim3 grid(Bn / 8);
    dim3 block(NTH);
    tblock_kernel<<<grid, block, smem_bytes>>>(x, bq, bk, bv, bp, b1, b2,
                                               g1, be1, g2, be2, out);
}

// round 5
// speedup vs baseline: 8.5570x; 1.0158x over previous
#include <cuda_runtime.h>
#include <cuda_fp16.h>
#include <math.h>
#include <stdint.h>

#define Bn   16384
#define TOK  128          // tokens per CTA (8 batches x 16)
#define LDH  72           // half stride (144B rows -> conflict-free ldmatrix)
#define LDF  68           // float stride for x2 buffer
#define NTH  256
#define EPSV 1e-5f
#define SCL  0.25f
#define MATH 4608         // 64*LDH halves per packed 64x64 matrix

// Packed fp16 weights: 16 head mats (Wq,Wk,Wv,Wp per head) + 4 W1 chunks + 4 W2 chunks
__device__ __align__(16) __half gWpack[24 * MATH];

// ---------------- PTX helpers ----------------
__device__ __forceinline__ uint32_t cvta_s(const void* p) {
    return (uint32_t)__cvta_generic_to_shared(p);
}
__device__ __forceinline__ void ldsm_x4(uint32_t* r, uint32_t a) {
    asm volatile("ldmatrix.sync.aligned.m8n8.x4.shared.b16 {%0,%1,%2,%3}, [%4];"
                 : "=r"(r[0]), "=r"(r[1]), "=r"(r[2]), "=r"(r[3]) : "r"(a));
}
__device__ __forceinline__ void ldsm_x4_t(uint32_t* r, uint32_t a) {
    asm volatile("ldmatrix.sync.aligned.m8n8.x4.trans.shared.b16 {%0,%1,%2,%3}, [%4];"
                 : "=r"(r[0]), "=r"(r[1]), "=r"(r[2]), "=r"(r[3]) : "r"(a));
}
__device__ __forceinline__ void mma16816(float* d, const uint32_t* a, const uint32_t* b) {
    asm volatile("mma.sync.aligned.m16n8k16.row.col.f32.f16.f16.f32 "
                 "{%0,%1,%2,%3},{%4,%5,%6,%7},{%8,%9},{%0,%1,%2,%3};"
                 : "+f"(d[0]), "+f"(d[1]), "+f"(d[2]), "+f"(d[3])
                 : "r"(a[0]), "r"(a[1]), "r"(a[2]), "r"(a[3]), "r"(b[0]), "r"(b[1]));
}
__device__ __forceinline__ uint32_t h2u(float a, float b) {
    __half2 h = __floats2half2_rn(a, b);
    return *(uint32_t*)&h;
}
__device__ __forceinline__ void cp_commit() { asm volatile("cp.async.commit_group;"); }
__device__ __forceinline__ void cp_wait0()  { asm volatile("cp.async.wait_group 0;"); }
__device__ __forceinline__ void cp_wait1()  { asm volatile("cp.async.wait_group 1;"); }
__device__ __forceinline__ void copy_async(__half* dst, const __half* src, int bytes, int tid) {
    uint32_t d = cvta_s(dst);
    const char* s = (const char*)src;
    for (int off = tid * 16; off < bytes; off += NTH * 16)
        asm volatile("cp.async.cg.shared.global [%0], [%1], 16;" :: "r"(d + off), "l"(s + off));
}

// ---------------- A-fragment cache + register-A GEMM ----------------
__device__ __forceinline__ void load_afrag(const __half* A, int mr0, int offA, uint32_t af[4][8]) {
    uint32_t aB = cvta_s(A);
#pragma unroll
    for (int i = 0; i < 4; ++i) {
        ldsm_x4(&af[i][0], aB + 2u * (uint32_t)(mr0 * LDH + i * 16 + offA));
        ldsm_x4(&af[i][4], aB + 2u * (uint32_t)((mr0 + 16) * LDH + i * 16 + offA));
    }
}
__device__ __forceinline__ void wgemm_rf(const uint32_t af[4][8], const __half* B,
                                         int nc0, int offA, float acc[2][4][4]) {
    uint32_t bB = cvta_s(B);
#pragma unroll
    for (int i = 0; i < 4; ++i) {
        uint32_t b0[4], b1[4];
        ldsm_x4_t(b0, bB + 2u * (uint32_t)(i * 16 * LDH + nc0 + offA));
        ldsm_x4_t(b1, bB + 2u * (uint32_t)(i * 16 * LDH + nc0 + 16 + offA));
#pragma unroll
        for (int mi = 0; mi < 2; ++mi) {
            const uint32_t* aa = &af[i][mi * 4];
            mma16816(acc[mi][0], aa, b0);
            mma16816(acc[mi][1], aa, b0 + 2);
            mma16816(acc[mi][2], aa, b1);
            mma16816(acc[mi][3], aa, b1 + 2);
        }
    }
}
__device__ __forceinline__ void wgemm(const __half* A, const __half* B,
                                      int mr0, int nc0, int offA, float acc[2][4][4]) {
    uint32_t af[4][8];
    load_afrag(A, mr0, offA, af);
    wgemm_rf(af, B, nc0, offA, acc);
}

__device__ __forceinline__ void init_bias(float acc[2][4][4], const float* bias,
                                          int nc0, int lane) {
    int c2 = 2 * (lane & 3);
#pragma unroll
    for (int j = 0; j < 4; ++j) {
        float2 bv = *(const float2*)(bias + nc0 + 8 * j + c2);
#pragma unroll
        for (int mi = 0; mi < 2; ++mi) {
            acc[mi][j][0] = bv.x; acc[mi][j][1] = bv.y;
            acc[mi][j][2] = bv.x; acc[mi][j][3] = bv.y;
        }
    }
}

__device__ __forceinline__ void store_half_tile(__half* C, int mr0, int nc0, int lane,
                                                const float acc[2][4][4], bool relu) {
    int r = lane >> 2, c2 = 2 * (lane & 3);
#pragma unroll
    for (int mi = 0; mi < 2; ++mi)
#pragma unroll
        for (int j = 0; j < 4; ++j) {
            float v0 = acc[mi][j][0], v1 = acc[mi][j][1];
            float v2 = acc[mi][j][2], v3 = acc[mi][j][3];
            if (relu) {
                v0 = fmaxf(v0, 0.f); v1 = fmaxf(v1, 0.f);
                v2 = fmaxf(v2, 0.f); v3 = fmaxf(v3, 0.f);
            }
            int row = mr0 + 16 * mi + r, col = nc0 + 8 * j + c2;
            *(__half2*)(C + row * LDH + col)       = __floats2half2_rn(v0, v1);
            *(__half2*)(C + (row + 8) * LDH + col) = __floats2half2_rn(v2, v3);
        }
}

// LayerNorm 64-wide rows (2 threads/row), fp32 src -> half dst (stride LDH)
__device__ __forceinline__ void layernorm_half(const float* __restrict__ src, int sstride,
                                               const float* __restrict__ g,
                                               const float* __restrict__ bb,
                                               __half* dst, int tid) {
    int r = tid >> 1, hf = tid & 1;
    const float* sp = src + r * sstride + hf * 32;
    float4 v[8];
#pragma unroll
    for (int i = 0; i < 8; ++i) v[i] = *(const float4*)(sp + i * 4);
    float s = 0.f, ss = 0.f;
#pragma unroll
    for (int i = 0; i < 8; ++i) {
        s  += v[i].x + v[i].y + v[i].z + v[i].w;
        ss += v[i].x * v[i].x + v[i].y * v[i].y + v[i].z * v[i].z + v[i].w * v[i].w;
    }
    s  += __shfl_xor_sync(0xffffffffu, s, 1);
    ss += __shfl_xor_sync(0xffffffffu, ss, 1);
    float mean = s * (1.f / 64.f);
    float inv  = rsqrtf(ss * (1.f / 64.f) - mean * mean + EPSV);
    __half* dp = dst + r * LDH + hf * 32;
#pragma unroll
    for (int i = 0; i < 8; ++i) {
        int d = hf * 32 + i * 4;
        float o0 = (v[i].x - mean) * inv * __ldg(g + d + 0) + __ldg(bb + d + 0);
        float o1 = (v[i].y - mean) * inv * __ldg(g + d + 1) + __ldg(bb + d + 1);
        float o2 = (v[i].z - mean) * inv * __ldg(g + d + 2) + __ldg(bb + d + 2);
        float o3 = (v[i].w - mean) * inv * __ldg(g + d + 3) + __ldg(bb + d + 3);
        *(__half2*)(dp + i * 4)     = __floats2half2_rn(o0, o1);
        *(__half2*)(dp + i * 4 + 2) = __floats2half2_rn(o2, o3);
    }
}

// per-warp causal attention for one batch (16x16)
__device__ __forceinline__ void attention_warp(__half* sQ, const __half* sK, const __half* sV,
                                               int w, int lane, int offA, int offK) {
    const int base = w * 16;
    uint32_t qB = cvta_s(sQ), kB = cvta_s(sK), vB = cvta_s(sV);

    float s0[4] = {0.f, 0.f, 0.f, 0.f};
    float s1[4] = {0.f, 0.f, 0.f, 0.f};
#pragma unroll
    for (int k0 = 0; k0 < 64; k0 += 16) {
        uint32_t aq[4], kb[4];
        ldsm_x4(aq, qB + 2u * (uint32_t)(base * LDH + k0 + offA));
        ldsm_x4(kb, kB + 2u * (uint32_t)(base * LDH + k0 + offK));
        mma16816(s0, aq, kb);
        mma16816(s1, aq, kb + 2);
    }
    const int r = lane >> 2, c2 = 2 * (lane & 3);

    float sc[2][4];
#pragma unroll
    for (int t = 0; t < 2; ++t) {
        const float* sv_ = t ? s1 : s0;
#pragma unroll
        for (int q = 0; q < 4; ++q) {
            int row = r + ((q >> 1) * 8);
            int col = 8 * t + c2 + (q & 1);
            sc[t][q] = (col <= row) ? sv_[q] * SCL : -1e30f;
        }
    }
    float m0 = fmaxf(fmaxf(sc[0][0], sc[0][1]), fmaxf(sc[1][0], sc[1][1]));
    float m1 = fmaxf(fmaxf(sc[0][2], sc[0][3]), fmaxf(sc[1][2], sc[1][3]));
    m0 = fmaxf(m0, __shfl_xor_sync(0xffffffffu, m0, 1));
    m0 = fmaxf(m0, __shfl_xor_sync(0xffffffffu, m0, 2));
    m1 = fmaxf(m1, __shfl_xor_sync(0xffffffffu, m1, 1));
    m1 = fmaxf(m1, __shfl_xor_sync(0xffffffffu, m1, 2));
    float p[2][4];
    float sum0 = 0.f, sum1 = 0.f;
#pragma unroll
    for (int t = 0; t < 2; ++t) {
        p[t][0] = __expf(sc[t][0] - m0); p[t][1] = __expf(sc[t][1] - m0);
        p[t][2] = __expf(sc[t][2] - m1); p[t][3] = __expf(sc[t][3] - m1);
        sum0 += p[t][0] + p[t][1];
        sum1 += p[t][2] + p[t][3];
    }
    sum0 += __shfl_xor_sync(0xffffffffu, sum0, 1);
    sum0 += __shfl_xor_sync(0xffffffffu, sum0, 2);
    sum1 += __shfl_xor_sync(0xffffffffu, sum1, 1);
    sum1 += __shfl_xor_sync(0xffffffffu, sum1, 2);
    float i0 = 1.f / sum0, i1 = 1.f / sum1;

    uint32_t aP[4];
    aP[0] = h2u(p[0][0] * i0, p[0][1] * i0);
    aP[1] = h2u(p[0][2] * i1, p[0][3] * i1);
    aP[2] = h2u(p[1][0] * i0, p[1][1] * i0);
    aP[3] = h2u(p[1][2] * i1, p[1][3] * i1);

    // ctx = P @ V -> overwrite sQ rows of this batch
#pragma unroll
    for (int d0 = 0; d0 < 64; d0 += 16) {
        uint32_t vb[4];
        ldsm_x4_t(vb, vB + 2u * (uint32_t)(base * LDH + d0 + offA));
        float c0f[4] = {0.f, 0.f, 0.f, 0.f};
        float c1f[4] = {0.f, 0.f, 0.f, 0.f};
        mma16816(c0f, aP, vb);
        mma16816(c1f, aP, vb + 2);
        *(__half2*)(sQ + (base + r) * LDH + d0 + c2)         = __floats2half2_rn(c0f[0], c0f[1]);
        *(__half2*)(sQ + (base + r + 8) * LDH + d0 + c2)     = __floats2half2_rn(c0f[2], c0f[3]);
        *(__half2*)(sQ + (base + r) * LDH + d0 + 8 + c2)     = __floats2half2_rn(c1f[0], c1f[1]);
        *(__half2*)(sQ + (base + r + 8) * LDH + d0 + 8 + c2) = __floats2half2_rn(c1f[2], c1f[3]);
    }
}

// ---------------- weight pack pre-kernel ----------------
__global__ void pack_weights(const float* __restrict__ Wq, const float* __restrict__ Wk,
                             const float* __restrict__ Wv, const float* __restrict__ Wp,
                             const float* __restrict__ W1, const float* __restrict__ W2) {
    int m = blockIdx.x, tid = threadIdx.x;
    const float* base;
    int stride;
    if (m < 16) {
        int h = m >> 2, t = m & 3;
        const float* w = (t == 0) ? Wq : (t == 1) ? Wk : (t == 2) ? Wv : Wp;
        base = w + h * 4096; stride = 64;
    } else if (m < 20) {
        base = W1 + (m - 16) * 64; stride = 256;   // W1[:, cc*64 .. +63]
    } else {
        base = W2 + (m - 20) * 4096; stride = 64;  // W2[cc*64 .. +63, :]
    }
    __half* dst = gWpack + m * MATH;
#pragma unroll
    for (int j = 0; j < 4; ++j) {
        int e = tid + j * 256;          // float4 unit 0..1023
        int k = e >> 4, c4 = (e & 15) * 4;
        float4 v = *(const float4*)(base + k * stride + c4);
        *(__half2*)(dst + k * LDH + c4)     = __floats2half2_rn(v.x, v.y);
        *(__half2*)(dst + k * LDH + c4 + 2) = __floats2half2_rn(v.z, v.w);
    }
}

// ---------------- main fused kernel ----------------
__global__ void __launch_bounds__(NTH, 2)
tblock_kernel(const float* __restrict__ x,
              const float* __restrict__ bq, const float* __restrict__ bk,
              const float* __restrict__ bv, const float* __restrict__ bp,
              const float* __restrict__ b1, const float* __restrict__ b2,
              const float* __restrict__ g1, const float* __restrict__ be1,
              const float* __restrict__ g2, const float* __restrict__ be2,
              float* __restrict__ out) {
    extern __shared__ __align__(16) char smraw[];
    __half* sH = (__half*)smraw;       // 128 x LDH
    __half* sQ = sH + TOK * LDH;
    __half* sK = sQ + TOK * LDH;
    __half* sV = sK + TOK * LDH;
    __half* sW = sV + TOK * LDH;       // 4 weight slots x MATH
    float*  x2 = (float*)sK;           // aliased: sK+sV dead after attention phase

    const int tid  = threadIdx.x;
    const int lane = tid & 31;
    const int w    = tid >> 5;
    const int g0   = blockIdx.x * TOK;

    const int mr0 = (w >> 1) * 32, nc0 = (w & 1) * 32;
    const int offA = (((lane >> 3) & 1) * 8 + (lane & 7)) * LDH + (lane >> 4) * 8;
    const int offK = ((lane >> 4) * 8 + (lane & 7)) * LDH + ((lane >> 3) & 1) * 8;

    // prefetch head-0 weights as TWO groups: G_A = Wq/Wk/Wv (slots 0-2), G_B = Wp (slot 3)
    copy_async(sW, gWpack, 3 * MATH * 2, tid);
    cp_commit();
    copy_async(sW + 3 * MATH, gWpack + 3 * MATH, MATH * 2, tid);
    cp_commit();

    // LN1: x -> sH (half)  (overlaps weight copies)
    layernorm_half(x + (size_t)g0 * 64, 64, g1, be1, sH, tid);
    cp_wait1();          // G_A(0) done; G_B(0) may still be in flight
    __syncthreads();

    // cache A fragments of sH (reused for all 12 QKV GEMMs)
    uint32_t ah[4][8];
    load_afrag(sH, mr0, offA, ah);

    float pacc[2][4][4];
    init_bias(pacc, bp, nc0, lane);

#pragma unroll 1
    for (int h = 0; h < 4; ++h) {
        // QKV from cached A frags (slots 0-2 resident & published)
        {
            float acc[2][4][4];
            init_bias(acc, bq + h * 64, nc0, lane);
            wgemm_rf(ah, sW, nc0, offA, acc);
            store_half_tile(sQ, mr0, nc0, lane, acc, false);
        }
        {
            float acc[2][4][4];
            init_bias(acc, bk + h * 64, nc0, lane);
            wgemm_rf(ah, sW + MATH, nc0, offA, acc);
            store_half_tile(sK, mr0, nc0, lane, acc, false);
        }
        {
            float acc[2][4][4];
            init_bias(acc, bv + h * 64, nc0, lane);
            wgemm_rf(ah, sW + 2 * MATH, nc0, offA, acc);
            store_half_tile(sV, mr0, nc0, lane, acc, false);
        }
        __syncthreads();   // QKV reads of slots 0-2 done; QKV stores published

        // G_A(h+1): slots 0-2 now dead -> prefetch next head's Wq/Wk/Wv
        if (h < 3) {
            copy_async(sW, gWpack + (h + 1) * 4 * MATH, 3 * MATH * 2, tid);
            cp_commit();
        }

        attention_warp(sQ, sK, sV, w, lane, offA, offK);

        cp_wait1();        // G_B(h) (slot 3 = Wp_h) done; G_A(h+1) may be in flight
        __syncthreads();   // publish slot 3 + order attention ctx stores before proj

        // pacc += ctx_h @ Wp_h
        wgemm(sQ, sW + 3 * MATH, mr0, nc0, offA, pacc);
        __syncthreads();   // proj reads of slot 3 + sQ done

        // G_B(h+1): slot 3 dead -> prefetch next head's Wp
        if (h < 3) {
            copy_async(sW + 3 * MATH, gWpack + (h + 1) * 4 * MATH + 3 * MATH, MATH * 2, tid);
            cp_commit();
            cp_wait1();      // G_A(h+1) done (G_B(h+1) may remain in flight)
            __syncthreads(); // publish slots 0-2 for next head's QKV
        }
    }

    // x2 = x + attn_out (fp32, aliased over sK/sV — safe: post-proj sync done)
    {
        const int r = lane >> 2, c2 = 2 * (lane & 3);
#pragma unroll
        for (int mi = 0; mi < 2; ++mi)
#pragma unroll
            for (int j = 0; j < 4; ++j) {
                int row = mr0 + 16 * mi + r, col = nc0 + 8 * j + c2;
                float2 xa = *(const float2*)(x + (size_t)(g0 + row) * 64 + col);
                float2 xb = *(const float2*)(x + (size_t)(g0 + row + 8) * 64 + col);
                x2[row * LDF + col]           = xa.x + pacc[mi][j][0];
                x2[row * LDF + col + 1]       = xa.y + pacc[mi][j][1];
                x2[(row + 8) * LDF + col]     = xb.x + pacc[mi][j][2];
                x2[(row + 8) * LDF + col + 1] = xb.y + pacc[mi][j][3];
            }
    }
    // prefetch FFN chunk 0 into slots 0,1 (overlaps x2 + LN2)
    copy_async(sW, gWpack + 16 * MATH, MATH * 2, tid);
    copy_async(sW + MATH, gWpack + 20 * MATH, MATH * 2, tid);
    cp_commit();
    __syncthreads();

    // LN2: x2 -> sH (half)
    layernorm_half(x2, LDF, g2, be2, sH, tid);
    __syncthreads();

    uint32_t ahf[4][8];
    load_afrag(sH, mr0, offA, ahf);

    float oacc[2][4][4];
    init_bias(oacc, b2, nc0, lane);

#pragma unroll 1
    for (int cc = 0; cc < 4; ++cc) {
        const __half* Wb = sW + (cc & 1) * 2 * MATH;   // slots {0,1} or {2,3}
        cp_wait0();
        __syncthreads();   // publish this chunk's weights; orders sQ overwrite below

        // hidden = relu(h2 @ W1c + b1c) -> sQ
        {
            float acc[2][4][4];
            init_bias(acc, b1 + cc * 64, nc0, lane);
            wgemm_rf(ahf, Wb, nc0, offA, acc);
            store_half_tile(sQ, mr0, nc0, lane, acc, true);
        }
        __syncthreads();   // hidden stores published for W2 gemm

        if (cc < 3) {
            __half* nb = sW + ((cc + 1) & 1) * 2 * MATH;
            copy_async(nb, gWpack + (16 + cc + 1) * MATH, MATH * 2, tid);
            copy_async(nb + MATH, gWpack + (20 + cc + 1) * MATH, MATH * 2, tid);
            cp_commit();
        }

        // oacc += hidden @ W2c  (no trailing sync: next iter's top sync orders sQ reuse)
        wgemm(sQ, Wb + MATH, mr0, nc0, offA, oacc);
    }

    // out = x2 + ffn  (x2 re-read by the same threads that wrote it: no sync needed)
    {
        const int r = lane >> 2, c2 = 2 * (lane & 3);
#pragma unroll
        for (int mi = 0; mi < 2; ++mi)
#pragma unroll
            for (int j = 0; j < 4; ++j) {
                int row = mr0 + 16 * mi + r, col = nc0 + 8 * j + c2;
                float2 o0, o1;
                o0.x = x2[row * LDF + col]           + oacc[mi][j][0];
                o0.y = x2[row * LDF + col + 1]       + oacc[mi][j][1];
                o1.x = x2[(row + 8) * LDF + col]     + oacc[mi][j][2];
                o1.y = x2[(row + 8) * LDF + col + 1] + oacc[mi][j][3];
                *(float2*)(out + (size_t)(g0 + row) * 64 + col)     = o0;
                *(float2*)(out + (size_t)(g0 + row + 8) * 64 + col) = o1;
            }
    }
}

extern "C" void kernel_launch(void* const* d_in, const int* in_sizes, int n_in,
                              void* d_out, int out_size) {
    const float* x   = (const float*)d_in[0];
    const float* Wq  = (const float*)d_in[1];
    const float* bq  = (const float*)d_in[2];
    const float* Wk  = (const float*)d_in[3];
    const float* bk  = (const float*)d_in[4];
    const float* Wv  = (const float*)d_in[5];
    const float* bv  = (const float*)d_in[6];
    const float* Wp  = (const float*)d_in[7];
    const float* bp  = (const float*)d_in[8];
    const float* W1  = (const float*)d_in[9];
    const float* b1  = (const float*)d_in[10];
    const float* W2  = (const float*)d_in[11];
    const float* b2  = (const float*)d_in[12];
    const float* g1  = (const float*)d_in[13];
    const float* be1 = (const float*)d_in[14];
    const float* g2  = (const float*)d_in[15];
    const float* be2 = (const float*)d_in[16];
    float* out = (float*)d_out;

    pack_weights<<<24, 256>>>(Wq, Wk, Wv, Wp, W1, W2);

    const int smem_bytes = (4 * TOK * LDH + 4 * MATH) * 2; // 110592
    cudaFuncSetAttribute(tblock_kernel, cudaFuncAttributeMaxDynamicSharedMemorySize, smem_bytes);

    dim3 grid(Bn / 8);
    dim3 block(NTH);
    tblock_kernel<<<grid, block, smem_bytes>>>(x, bq, bk, bv, bp, b1, b2,
                                               g1, be1, g2, be2, out);
}